// round 4
// baseline (speedup 1.0000x reference)
#include <cuda_runtime.h>
#include <cuda_bf16.h>
#include <cstdint>

// ---------------------------------------------------------------------------
// VFNet: FNet-style ViT forward.
// B=64, C=3, H=W=512, P=16, D=256, NP=1024, T=1025, HID=1024, L=6, NC=1000
// fft2 real part computed as DFT GEMMs with real-input symmetry (half freqs
// on both axes), batch folded into GEMM-N for the token-axis transform.
// ---------------------------------------------------------------------------

#define BATCH 64
#define TOK   1025
#define DIM   256
#define HID   1024
#define LAYERS 6
#define NC    1000
#define NF    129          // dim-axis frequencies kept (0..128)
#define MF    513          // token-axis frequencies kept (0..512)
#define ROWS  (BATCH*TOK)  // 65600
#define NPAT  1024
#define KPE   768          // patch embed K = 3*16*16
#define EPS   1e-5f

// ------------------------------ scratch -----------------------------------
__device__ float g_t   [ROWS*DIM];          // 67 MB  residual stream
__device__ float g_h   [ROWS*DIM];          // 67 MB  LN output
__device__ float g_X   [BATCH*NPAT*KPE];    // 201 MB im2col
__device__ float g_tok [BATCH*NPAT*DIM];    // 67 MB  patch embed out
__device__ float g_wT  [KPE*DIM];
__device__ float g_C   [TOK*BATCH*NF];      // 33.8 MB  [j][b][nf]
__device__ float g_S   [TOK*BATCH*NF];
__device__ float g_U   [MF*BATCH*NF];       // 16.9 MB  [m][b*NF+nf]
__device__ float g_V   [MF*BATCH*NF];
__device__ float g_hid [ROWS*HID];          // 269 MB
__device__ float g_cosA[DIM*NF];
__device__ float g_sinA[DIM*NF];
__device__ float g_cosB[MF*TOK];
__device__ float g_sinB[MF*TOK];
__device__ float g_pool[BATCH*DIM];

// --------------------------- generic fp32 SGEMM ---------------------------
// C[MxN] = A[MxK] (row-major, lda) * B[KxN] (row-major, ldb), tiled 128x128x8,
// 256 threads, 8x8 per thread. Fully guarded edges.
// modes: 0 = store (+bias)          C[r*ldc+n]
//        1 = scatter store          C[(r%tdim)*os1 + (r/tdim)*os2 + n]
//        2 = bias + leaky_relu(.01) C[r*ldc+n]
//        3 = bias + residual add    C[r*ldc+n] = res[r*ldc+n] + acc + bias
__global__ __launch_bounds__(256) void sgemm_kernel(
    const float* __restrict__ A, int lda,
    const float* __restrict__ B, int ldb,
    float* __restrict__ Cout, int ldc,
    int M, int N, int K,
    const float* __restrict__ bias,
    const float* __restrict__ res,
    int mode, int tdim, int os1, int os2)
{
    __shared__ float As[8][132];   // padded: conflict-free stores/loads
    __shared__ float Bs[8][128];

    const int tid = threadIdx.x;
    const int bm = blockIdx.y * 128;
    const int bn = blockIdx.x * 128;
    const int tx = tid & 15;       // 0..15 -> 8 cols each
    const int ty = tid >> 4;       // 0..15 -> 8 rows each

    float acc[8][8];
#pragma unroll
    for (int i = 0; i < 8; i++)
#pragma unroll
        for (int j = 0; j < 8; j++) acc[i][j] = 0.f;

    const int aRow = tid >> 1;           // 0..127
    const int aCol = (tid & 1) * 4;      // 0 or 4
    const int bRowBase = tid >> 7;       // 0 or 1
    const int bCol = tid & 127;

    const int nIter = (K + 7) >> 3;
    for (int t0 = 0; t0 < nIter; ++t0) {
        const int k0 = t0 << 3;
        // load A tile (128 x 8) -> As[k][m]
        {
            const int gm = bm + aRow;
            const bool mok = (gm < M);
            const float* ap = A + (size_t)gm * lda + k0 + aCol;
#pragma unroll
            for (int i = 0; i < 4; i++) {
                const int gk = k0 + aCol + i;
                float v = 0.f;
                if (mok && gk < K) v = ap[i];
                As[aCol + i][aRow] = v;
            }
        }
        // load B tile (8 x 128) -> Bs[k][n]
        {
            const int gn = bn + bCol;
            const bool nok = (gn < N);
#pragma unroll
            for (int i = 0; i < 4; i++) {
                const int k = bRowBase + 2 * i;
                const int gk = k0 + k;
                float v = 0.f;
                if (nok && gk < K) v = B[(size_t)gk * ldb + gn];
                Bs[k][bCol] = v;
            }
        }
        __syncthreads();
#pragma unroll
        for (int k = 0; k < 8; k++) {
            float ra[8], rb[8];
#pragma unroll
            for (int i = 0; i < 8; i++) ra[i] = As[k][ty * 8 + i];
#pragma unroll
            for (int j = 0; j < 8; j++) rb[j] = Bs[k][tx * 8 + j];
#pragma unroll
            for (int i = 0; i < 8; i++)
#pragma unroll
                for (int j = 0; j < 8; j++) acc[i][j] += ra[i] * rb[j];
        }
        __syncthreads();
    }

    // epilogue
#pragma unroll
    for (int i = 0; i < 8; i++) {
        const int r = bm + ty * 8 + i;
        if (r >= M) continue;
        size_t rowoff;
        if (mode == 1) rowoff = (size_t)(r % tdim) * os1 + (size_t)(r / tdim) * os2;
        else           rowoff = (size_t)r * ldc;
#pragma unroll
        for (int j = 0; j < 8; j++) {
            const int n = bn + tx * 8 + j;
            if (n >= N) continue;
            float v = acc[i][j];
            if (bias) v += bias[n];
            if (mode == 2) v = v > 0.f ? v : 0.01f * v;
            if (mode == 3) v += res[rowoff + n];
            Cout[rowoff + n] = v;
        }
    }
}

// ------------------------------ small kernels ------------------------------
__global__ void fill_basisA_kernel(float* __restrict__ ca, float* __restrict__ sa)
{
    int idx = blockIdx.x * 256 + threadIdx.x;
    if (idx >= DIM * NF) return;
    int k = idx / NF, n = idx % NF;
    int r = (k * n) & 255;
    float a = 2.0f * (float)r / 256.0f;
    ca[idx] = cospif(a);
    sa[idx] = sinpif(a);
}

__global__ void fill_basisB_kernel(float* __restrict__ cb, float* __restrict__ sb)
{
    int idx = blockIdx.x * 256 + threadIdx.x;
    if (idx >= MF * TOK) return;
    int m = idx / TOK, j = idx % TOK;
    int r = (m * j) % TOK;
    float a = 2.0f * (float)r / (float)TOK;
    cb[idx] = cospif(a);
    sb[idx] = sinpif(a);
}

__global__ void transpose_w_kernel(const float* __restrict__ w, float* __restrict__ wT)
{
    int idx = blockIdx.x * 256 + threadIdx.x;
    if (idx >= DIM * KPE) return;
    int d = idx / KPE, k = idx % KPE;
    wT[k * DIM + d] = w[idx];
}

__global__ void im2col_kernel(const float* __restrict__ x, float* __restrict__ X)
{
    size_t idx = (size_t)blockIdx.x * 256 + threadIdx.x;
    if (idx >= (size_t)BATCH * NPAT * KPE) return;
    int k = (int)(idx % KPE);
    size_t r = idx / KPE;
    int pr = (int)(r % NPAT);
    int b = (int)(r / NPAT);
    int gh = pr >> 5, gw = pr & 31;
    int c = k >> 8, rem = k & 255, p = rem >> 4, q = rem & 15;
    X[idx] = x[(((size_t)(b * 3 + c) * 512) + gh * 16 + p) * 512 + gw * 16 + q];
}

__global__ void assemble_kernel(const float* __restrict__ tok, const float* __restrict__ cls,
                                const float* __restrict__ pos, float* __restrict__ t)
{
    size_t idx = (size_t)blockIdx.x * 256 + threadIdx.x;
    if (idx >= (size_t)ROWS * DIM) return;
    int n = (int)(idx & 255);
    size_t r = idx >> 8;
    int j = (int)(r % TOK);
    int b = (int)(r / TOK);
    float v = (j == 0) ? cls[n] : tok[((size_t)b * NPAT + (j - 1)) * DIM + n];
    t[idx] = v + pos[j * DIM + n];
}

__global__ void ln_kernel(const float* __restrict__ in, float* __restrict__ out,
                          const float* __restrict__ s, const float* __restrict__ bb, int rows)
{
    const int warp = threadIdx.x >> 5;
    const int lane = threadIdx.x & 31;
    const int row = blockIdx.x * 8 + warp;
    if (row >= rows) return;
    const float* p = in + (size_t)row * DIM;
    float v[8];
    float sum = 0.f;
#pragma unroll
    for (int i = 0; i < 8; i++) { v[i] = p[lane + 32 * i]; sum += v[i]; }
#pragma unroll
    for (int o = 16; o; o >>= 1) sum += __shfl_xor_sync(0xffffffffu, sum, o);
    const float mean = sum * (1.f / 256.f);
    float var = 0.f;
#pragma unroll
    for (int i = 0; i < 8; i++) { float d = v[i] - mean; var += d * d; }
#pragma unroll
    for (int o = 16; o; o >>= 1) var += __shfl_xor_sync(0xffffffffu, var, o);
    const float rs = rsqrtf(var * (1.f / 256.f) + EPS);
    float* q = out + (size_t)row * DIM;
#pragma unroll
    for (int i = 0; i < 8; i++) {
        int n = lane + 32 * i;
        q[n] = (v[i] - mean) * rs * s[n] + bb[n];
    }
}

// Scatter the half-spectrum U,V back to the full 1025x256 grid, added into t.
// out[m,n]      = U - V
// out[m,256-n]  = U + V     (n in 1..127)
// out[1025-m,n] = U + V     (m in 1..512)
// out[1025-m,256-n] = U - V
__global__ void scatter_kernel(const float* __restrict__ U, const float* __restrict__ V,
                               float* __restrict__ t)
{
    int idx = blockIdx.x * 256 + threadIdx.x;
    if (idx >= MF * BATCH * NF) return;
    int nf = idx % NF;
    int tmp = idx / NF;
    int b = tmp % BATCH;
    int m = tmp / BATCH;
    size_t uoff = (size_t)m * (BATCH * NF) + b * NF + nf;
    float u = U[uoff];
    float v = V[uoff];
    float d1 = u - v, d2 = u + v;
    float* tb = t + (size_t)b * TOK * DIM;
    tb[m * DIM + nf] += d1;
    bool nmir = (nf >= 1 && nf <= 127);
    if (nmir) tb[m * DIM + (DIM - nf)] += d2;
    if (m >= 1) {
        int m2 = TOK - m;
        tb[m2 * DIM + nf] += d2;
        if (nmir) tb[m2 * DIM + (DIM - nf)] += d1;
    }
}

__global__ void pool_kernel(const float* __restrict__ t, float* __restrict__ pooled)
{
    int b = blockIdx.x, n = threadIdx.x;
    const float* p = t + (size_t)b * TOK * DIM + n;
    float s0 = 0.f, s1 = 0.f, s2 = 0.f, s3 = 0.f;
    int j = 0;
    for (; j + 4 <= TOK; j += 4) {
        s0 += p[(size_t)(j + 0) * DIM];
        s1 += p[(size_t)(j + 1) * DIM];
        s2 += p[(size_t)(j + 2) * DIM];
        s3 += p[(size_t)(j + 3) * DIM];
    }
    for (; j < TOK; j++) s0 += p[(size_t)j * DIM];
    pooled[b * DIM + n] = (s0 + s1 + s2 + s3) * (1.0f / (float)TOK);
}

__global__ void head_kernel(const float* __restrict__ pooled,
                            const float* __restrict__ hs, const float* __restrict__ hb,
                            const float* __restrict__ W, const float* __restrict__ wb,
                            float* __restrict__ out)
{
    __shared__ float sln[DIM];
    __shared__ float red[8];
    const int b = blockIdx.x, tid = threadIdx.x;
    const int lane = tid & 31, warp = tid >> 5;

    float x = pooled[b * DIM + tid];
    // block mean
    float sum = x;
#pragma unroll
    for (int o = 16; o; o >>= 1) sum += __shfl_xor_sync(0xffffffffu, sum, o);
    if (lane == 0) red[warp] = sum;
    __syncthreads();
    float mean;
    {
        float t0 = (lane < 8) ? red[lane] : 0.f;
#pragma unroll
        for (int o = 4; o; o >>= 1) t0 += __shfl_xor_sync(0xffffffffu, t0, o);
        mean = __shfl_sync(0xffffffffu, t0, 0) * (1.f / 256.f);
    }
    __syncthreads();
    // block var
    float d = x - mean;
    float vv = d * d;
#pragma unroll
    for (int o = 16; o; o >>= 1) vv += __shfl_xor_sync(0xffffffffu, vv, o);
    if (lane == 0) red[warp] = vv;
    __syncthreads();
    float var;
    {
        float t0 = (lane < 8) ? red[lane] : 0.f;
#pragma unroll
        for (int o = 4; o; o >>= 1) t0 += __shfl_xor_sync(0xffffffffu, t0, o);
        var = __shfl_sync(0xffffffffu, t0, 0) * (1.f / 256.f);
    }
    float rs = rsqrtf(var + EPS);
    sln[tid] = d * rs * hs[tid] + hb[tid];
    __syncthreads();

    // logits: each thread owns up to 4 classes
    float lg[4];
#pragma unroll
    for (int jj = 0; jj < 4; jj++) {
        int n = tid + jj * 256;
        float a = 0.f;
        if (n < NC) {
            for (int k = 0; k < DIM; k++) a += sln[k] * W[(size_t)k * NC + n];
            a += wb[n];
        }
        lg[jj] = a;
    }
    // softmax: block max
    float mx = -3.4e38f;
#pragma unroll
    for (int jj = 0; jj < 4; jj++) if (tid + jj * 256 < NC && lg[jj] > mx) mx = lg[jj];
#pragma unroll
    for (int o = 16; o; o >>= 1) mx = fmaxf(mx, __shfl_xor_sync(0xffffffffu, mx, o));
    __syncthreads();
    if (lane == 0) red[warp] = mx;
    __syncthreads();
    {
        float t0 = (lane < 8) ? red[lane] : -3.4e38f;
#pragma unroll
        for (int o = 4; o; o >>= 1) t0 = fmaxf(t0, __shfl_xor_sync(0xffffffffu, t0, o));
        mx = __shfl_sync(0xffffffffu, t0, 0);
    }
    float es = 0.f;
#pragma unroll
    for (int jj = 0; jj < 4; jj++) {
        int n = tid + jj * 256;
        if (n < NC) { lg[jj] = expf(lg[jj] - mx); es += lg[jj]; }
    }
#pragma unroll
    for (int o = 16; o; o >>= 1) es += __shfl_xor_sync(0xffffffffu, es, o);
    __syncthreads();
    if (lane == 0) red[warp] = es;
    __syncthreads();
    {
        float t0 = (lane < 8) ? red[lane] : 0.f;
#pragma unroll
        for (int o = 4; o; o >>= 1) t0 += __shfl_xor_sync(0xffffffffu, t0, o);
        es = __shfl_sync(0xffffffffu, t0, 0);
    }
    float inv = 1.f / es;
#pragma unroll
    for (int jj = 0; jj < 4; jj++) {
        int n = tid + jj * 256;
        if (n < NC) out[(size_t)b * NC + n] = lg[jj] * inv;
    }
}

// ------------------------------ launch ------------------------------------
static inline void run_gemm(const float* A, int lda, const float* B, int ldb,
                            float* C, int ldc, int M, int N, int K,
                            const float* bias, const float* res, int mode,
                            int tdim = 1, int os1 = 0, int os2 = 0)
{
    dim3 grid((N + 127) / 128, (M + 127) / 128);
    sgemm_kernel<<<grid, 256>>>(A, lda, B, ldb, C, ldc, M, N, K, bias, res,
                                mode, tdim, os1, os2);
}

extern "C" void kernel_launch(void* const* d_in, const int* in_sizes, int n_in,
                              void* d_out, int out_size)
{
    const float* x       = (const float*)d_in[0];
    const float* conv_w  = (const float*)d_in[1];
    const float* conv_b  = (const float*)d_in[2];
    const float* pos_emb = (const float*)d_in[3];
    const float* cls_tok = (const float*)d_in[4];
    const float* ln1_s   = (const float*)d_in[5];
    const float* ln1_b   = (const float*)d_in[6];
    const float* ln2_s   = (const float*)d_in[7];
    const float* ln2_b   = (const float*)d_in[8];
    const float* w1      = (const float*)d_in[9];
    const float* b1      = (const float*)d_in[10];
    const float* w2      = (const float*)d_in[11];
    const float* b2      = (const float*)d_in[12];
    const float* h_ln_s  = (const float*)d_in[13];
    const float* h_ln_b  = (const float*)d_in[14];
    const float* head_w  = (const float*)d_in[15];
    const float* head_b  = (const float*)d_in[16];
    float* out = (float*)d_out;

    float *t, *h, *X, *tok, *wT, *C_, *S_, *U, *V, *hid;
    float *cA, *sA, *cB, *sB, *pl;
    cudaGetSymbolAddress((void**)&t,   g_t);
    cudaGetSymbolAddress((void**)&h,   g_h);
    cudaGetSymbolAddress((void**)&X,   g_X);
    cudaGetSymbolAddress((void**)&tok, g_tok);
    cudaGetSymbolAddress((void**)&wT,  g_wT);
    cudaGetSymbolAddress((void**)&C_,  g_C);
    cudaGetSymbolAddress((void**)&S_,  g_S);
    cudaGetSymbolAddress((void**)&U,   g_U);
    cudaGetSymbolAddress((void**)&V,   g_V);
    cudaGetSymbolAddress((void**)&hid, g_hid);
    cudaGetSymbolAddress((void**)&cA,  g_cosA);
    cudaGetSymbolAddress((void**)&sA,  g_sinA);
    cudaGetSymbolAddress((void**)&cB,  g_cosB);
    cudaGetSymbolAddress((void**)&sB,  g_sinB);
    cudaGetSymbolAddress((void**)&pl,  g_pool);

    // basis + weights prep
    fill_basisA_kernel<<<(DIM * NF + 255) / 256, 256>>>(cA, sA);
    fill_basisB_kernel<<<(MF * TOK + 255) / 256, 256>>>(cB, sB);
    transpose_w_kernel<<<(DIM * KPE + 255) / 256, 256>>>(conv_w, wT);

    // patch embed
    im2col_kernel<<<(int)(((size_t)BATCH * NPAT * KPE + 255) / 256), 256>>>(x, X);
    run_gemm(X, KPE, wT, DIM, tok, DIM, BATCH * NPAT, DIM, KPE, conv_b, nullptr, 0);
    assemble_kernel<<<(int)(((size_t)ROWS * DIM + 255) / 256), 256>>>(tok, cls_tok, pos_emb, t);

    for (int i = 0; i < LAYERS; i++) {
        // --- FNet mixing ---
        ln_kernel<<<(ROWS + 7) / 8, 256>>>(t, h, ln1_s + i * DIM, ln1_b + i * DIM, ROWS);
        // dim-axis DFT (half spectrum), scattered to [j][b][nf]
        run_gemm(h, DIM, cA, NF, C_, 0, ROWS, NF, DIM, nullptr, nullptr, 1,
                 TOK, BATCH * NF, NF);
        run_gemm(h, DIM, sA, NF, S_, 0, ROWS, NF, DIM, nullptr, nullptr, 1,
                 TOK, BATCH * NF, NF);
        // token-axis DFT (half spectrum), batch folded into N
        run_gemm(cB, TOK, C_, BATCH * NF, U, BATCH * NF, MF, BATCH * NF, TOK,
                 nullptr, nullptr, 0);
        run_gemm(sB, TOK, S_, BATCH * NF, V, BATCH * NF, MF, BATCH * NF, TOK,
                 nullptr, nullptr, 0);
        scatter_kernel<<<(MF * BATCH * NF + 255) / 256, 256>>>(U, V, t);

        // --- FFN ---
        ln_kernel<<<(ROWS + 7) / 8, 256>>>(t, h, ln2_s + i * DIM, ln2_b + i * DIM, ROWS);
        run_gemm(h, DIM, w1 + (size_t)i * DIM * HID, HID, hid, HID,
                 ROWS, HID, DIM, b1 + i * HID, nullptr, 2);
        run_gemm(hid, HID, w2 + (size_t)i * HID * DIM, DIM, t, DIM,
                 ROWS, DIM, HID, b2 + i * DIM, t, 3);
    }

    pool_kernel<<<BATCH, DIM>>>(t, pl);
    head_kernel<<<BATCH, DIM>>>(pl, h_ln_s, h_ln_b, head_w, head_b, out);
}

// round 6
// speedup vs baseline: 1.5606x; 1.5606x over previous
#include <cuda_runtime.h>
#include <cuda_bf16.h>
#include <cstdint>

// ---------------------------------------------------------------------------
// VFNet: all GEMMs as bf16x3 split-precision warp-level mma.sync (HMMA).
// B=64, TOK=1025, D=256, HID=1024, L=6, NC=1000
// DFT via half-spectrum cos/sin basis GEMMs; fused epilogues.
// ---------------------------------------------------------------------------

#define BATCH 64
#define TOK   1025
#define DIM   256
#define HIDN  1024
#define LAYERS 6
#define NC    1000
#define NF    129
#define MF    513
#define ROWS  (BATCH*TOK)       // 65600
#define NPAT  1024
#define KPE   768
#define TOKP  1088              // TOK padded to 32-multiple (34*32)
#define BNF   (BATCH*NF)        // 8256
#define EPS   1e-5f

// ------------------------------ scratch -----------------------------------
__device__ __align__(128) float          g_t   [ROWS*DIM];
__device__ __align__(128) __nv_bfloat16  g_hH  [ROWS*DIM];
__device__ __align__(128) __nv_bfloat16  g_hL  [ROWS*DIM];
__device__ __align__(128) __nv_bfloat16  g_XH  [BATCH*NPAT*KPE];
__device__ __align__(128) __nv_bfloat16  g_XL  [BATCH*NPAT*KPE];
__device__ __align__(128) __nv_bfloat16  g_hidH[ROWS*HIDN];
__device__ __align__(128) __nv_bfloat16  g_hidL[ROWS*HIDN];
__device__ __align__(128) __nv_bfloat16  g_CH  [BNF*TOKP];
__device__ __align__(128) __nv_bfloat16  g_CL  [BNF*TOKP];
__device__ __align__(128) __nv_bfloat16  g_SH  [BNF*TOKP];
__device__ __align__(128) __nv_bfloat16  g_SL  [BNF*TOKP];
__device__ __align__(128) float          g_U   [MF*BNF];
__device__ __align__(128) float          g_V   [MF*BNF];
__device__ __align__(128) __nv_bfloat16  g_cwH [DIM*KPE],  g_cwL [DIM*KPE];
__device__ __align__(128) __nv_bfloat16  g_bAH [258*DIM],  g_bAL [258*DIM];
__device__ __align__(128) __nv_bfloat16  g_cBH [MF*TOKP],  g_cBL [MF*TOKP];
__device__ __align__(128) __nv_bfloat16  g_sBH [MF*TOKP],  g_sBL [MF*TOKP];
__device__ __align__(128) __nv_bfloat16  g_w1H [LAYERS*HIDN*DIM], g_w1L [LAYERS*HIDN*DIM];
__device__ __align__(128) __nv_bfloat16  g_w2H [LAYERS*DIM*HIDN], g_w2L [LAYERS*DIM*HIDN];
__device__ __align__(128) float          g_pool[BATCH*DIM];

// --------------------------- PTX helpers -----------------------------------
__device__ __forceinline__ uint32_t smem_u32(const void* p) {
    uint32_t a;
    asm("{ .reg .u64 t; cvta.to.shared.u64 t, %1; cvt.u32.u64 %0, t; }" : "=r"(a) : "l"(p));
    return a;
}
__device__ __forceinline__ void cp16(uint32_t dst, const void* src, bool v) {
    asm volatile("cp.async.cg.shared.global [%0], [%1], 16, %2;"
                 :: "r"(dst), "l"(src), "r"(v ? 16 : 0) : "memory");
}
#define CP_COMMIT() asm volatile("cp.async.commit_group;" ::: "memory")
#define CP_WAIT(n)  asm volatile("cp.async.wait_group %0;" :: "n"(n) : "memory")

#define LDSM4(r, addr) \
    asm volatile("ldmatrix.sync.aligned.m8n8.x4.shared.b16 {%0,%1,%2,%3}, [%4];" \
                 : "=r"((r)[0]), "=r"((r)[1]), "=r"((r)[2]), "=r"((r)[3]) : "r"(addr))

#define MMA(c, a, b0, b1) \
    asm volatile("mma.sync.aligned.m16n8k16.row.col.f32.bf16.bf16.f32 " \
                 "{%0,%1,%2,%3}, {%4,%5,%6,%7}, {%8,%9}, {%0,%1,%2,%3};" \
                 : "+f"((c)[0]), "+f"((c)[1]), "+f"((c)[2]), "+f"((c)[3]) \
                 : "r"((a)[0]), "r"((a)[1]), "r"((a)[2]), "r"((a)[3]), \
                   "r"(b0), "r"(b1))

// SMEM: per stage Ah|Al|Bh|Bl, each 128 rows x 32 bf16, row stride 80 B (pad).
#define ROWB   80
#define MATB   (128*ROWB)        // 10240
#define STAGEB (4*MATB)          // 40960
#define NSTAGE 3
#define SMEM_TOTAL (NSTAGE*STAGEB)

// epilogue modes
#define M_PATCH 0
#define M_DFT1  1
#define M_F32   2
#define M_FFN1  3
#define M_FFN2  4

// --------------------------- mma.sync GEMM ---------------------------------
// C[M x Nvalid] = Apair[M x K] (K-major) * Bpair[Nvalid x K]^T, bf16x3 split.
__global__ __launch_bounds__(256, 1) void gemm_mma(
    const __nv_bfloat16* __restrict__ Ah, const __nv_bfloat16* __restrict__ Al, int lda,
    const __nv_bfloat16* __restrict__ Bh, const __nv_bfloat16* __restrict__ Bl, int ldb,
    int M, int Nvalid, int K, int mode, int ldc,
    const float* __restrict__ bias, const float* __restrict__ extra,
    float* __restrict__ outf,
    __nv_bfloat16* __restrict__ o0, __nv_bfloat16* __restrict__ o1,
    __nv_bfloat16* __restrict__ o2, __nv_bfloat16* __restrict__ o3)
{
    extern __shared__ char smc[];
    const uint32_t sb = smem_u32(smc);
    const int tid  = threadIdx.x;
    const int lane = tid & 31;
    const int wid  = tid >> 5;
    const int wm   = wid & 3;      // 4 warps along M (32 rows each)
    const int wn   = wid >> 2;     // 2 warps along N (64 cols each)
    const int mBase = blockIdx.y * 128;
    const int nBase = blockIdx.x * 128;

    const int NCH = K >> 5;

    // ---- stage loader ----
    auto load_stage = [&](int c) {
        const int k0  = c << 5;
        const uint32_t stg = sb + (uint32_t)(c % NSTAGE) * STAGEB;
#pragma unroll
        for (int t = 0; t < 8; t++) {
            const int idx  = tid + t * 256;
            const int mat  = idx >> 9;          // 0 Ah, 1 Al, 2 Bh, 3 Bl
            const int v    = idx & 511;
            const int row  = v >> 2;
            const int chk  = v & 3;
            const uint32_t dst = stg + mat * MATB + row * ROWB + chk * 16;
            const __nv_bfloat16* src;
            bool valid;
            if (mat < 2) {
                const int gm = mBase + row;
                valid = gm < M;
                const int r2 = valid ? gm : 0;
                src = (mat ? Al : Ah) + (size_t)r2 * lda + k0 + chk * 8;
            } else {
                const int gn = nBase + row;
                valid = gn < Nvalid;
                const int r2 = valid ? gn : 0;
                src = (mat == 2 ? Bh : Bl) + (size_t)r2 * ldb + k0 + chk * 8;
            }
            cp16(dst, src, valid);
        }
    };

    float acc[2][8][4];
#pragma unroll
    for (int mt = 0; mt < 2; mt++)
#pragma unroll
        for (int nt = 0; nt < 8; nt++)
#pragma unroll
            for (int e = 0; e < 4; e++) acc[mt][nt][e] = 0.f;

    // prologue
    for (int c = 0; c < NSTAGE - 1 && c < NCH; c++) { load_stage(c); CP_COMMIT(); }

    for (int c = 0; c < NCH; c++) {
        if (c + NSTAGE - 1 < NCH) { load_stage(c + NSTAGE - 1); CP_COMMIT(); }
        {
            int ahead = NCH - 1 - c;
            if (ahead > NSTAGE - 2) ahead = NSTAGE - 2;
            if (ahead >= 2)      CP_WAIT(2);
            else if (ahead == 1) CP_WAIT(1);
            else                 CP_WAIT(0);
        }
        __syncthreads();

        const uint32_t stg = sb + (uint32_t)(c % NSTAGE) * STAGEB;
        const uint32_t baA = stg;
        const uint32_t baB = stg + 2 * MATB;

#pragma unroll
        for (int ks = 0; ks < 2; ks++) {
            uint32_t aH[2][4], aL[2][4];
#pragma unroll
            for (int mt = 0; mt < 2; mt++) {
                const int row = wm * 32 + mt * 16 + (lane & 15);
                const int chk = ks * 2 + (lane >> 4);
                const uint32_t ad = baA + row * ROWB + chk * 16;
                LDSM4(aH[mt], ad);
                LDSM4(aL[mt], ad + MATB);
            }
            uint32_t bH[4][4], bL[4][4];
#pragma unroll
            for (int nt2 = 0; nt2 < 4; nt2++) {
                const int row = wn * 64 + nt2 * 16 + ((lane >> 4) << 3) + (lane & 7);
                const int chk = ks * 2 + ((lane >> 3) & 1);
                const uint32_t ad = baB + row * ROWB + chk * 16;
                LDSM4(bH[nt2], ad);
                LDSM4(bL[nt2], ad + MATB);
            }
#pragma unroll
            for (int mt = 0; mt < 2; mt++)
#pragma unroll
                for (int nt = 0; nt < 8; nt++) {
                    const int n2 = nt >> 1, hb = (nt & 1) * 2;
                    MMA(acc[mt][nt], aH[mt], bH[n2][hb], bH[n2][hb + 1]);
                    MMA(acc[mt][nt], aH[mt], bL[n2][hb], bL[n2][hb + 1]);
                    MMA(acc[mt][nt], aL[mt], bH[n2][hb], bH[n2][hb + 1]);
                }
        }
        __syncthreads();
    }

    // ------------------------------ epilogue -------------------------------
#pragma unroll
    for (int mt = 0; mt < 2; mt++) {
#pragma unroll
        for (int nt = 0; nt < 8; nt++) {
#pragma unroll
            for (int e = 0; e < 4; e++) {
                const int gm = mBase + wm * 32 + mt * 16 + (lane >> 2) + ((e >> 1) << 3);
                const int n  = nBase + wn * 64 + nt * 8 + ((lane & 3) << 1) + (e & 1);
                if (gm >= M || n >= Nvalid) continue;
                const float val = acc[mt][nt][e];
                if (mode == M_PATCH) {
                    const int b = gm >> 10, p = gm & 1023;
                    outf[((size_t)(b * TOK + p + 1)) * DIM + n] =
                        val + bias[n] + extra[(size_t)(p + 1) * DIM + n];
                } else if (mode == M_DFT1) {
                    const bool isCos = (gm < NF);
                    const int nf = isCos ? gm : gm - NF;
                    const int b = n / TOK;
                    const int j = n - b * TOK;
                    const size_t off = ((size_t)(b * NF + nf)) * TOKP + j;
                    const __nv_bfloat16 hi = __float2bfloat16(val);
                    if (isCos) { o0[off] = hi; o1[off] = __float2bfloat16(val - __bfloat162float(hi)); }
                    else       { o2[off] = hi; o3[off] = __float2bfloat16(val - __bfloat162float(hi)); }
                } else if (mode == M_F32) {
                    outf[(size_t)gm * ldc + n] = val;
                } else if (mode == M_FFN1) {
                    float v = val + bias[n];
                    v = v > 0.f ? v : 0.01f * v;
                    const size_t off = (size_t)gm * ldc + n;
                    const __nv_bfloat16 hi = __float2bfloat16(v);
                    o0[off] = hi;
                    o1[off] = __float2bfloat16(v - __bfloat162float(hi));
                } else { // M_FFN2
                    const size_t off = (size_t)gm * ldc + n;
                    outf[off] = outf[off] + val + bias[n];
                }
            }
        }
    }
}

// ------------------------------ prep kernels --------------------------------
__device__ __forceinline__ void store_pair(__nv_bfloat16* h, __nv_bfloat16* l,
                                           size_t i, float v) {
    const __nv_bfloat16 hi = __float2bfloat16(v);
    h[i] = hi;
    l[i] = __float2bfloat16(v - __bfloat162float(hi));
}

__global__ void gen_basisA(__nv_bfloat16* bh, __nv_bfloat16* bl) {
    int idx = blockIdx.x * 256 + threadIdx.x;
    if (idx >= 258 * DIM) return;
    int m = idx / DIM, k = idx % DIM;
    int nf = (m < NF) ? m : m - NF;
    int rr = (k * nf) & 255;
    float a = 2.0f * (float)rr / 256.0f;
    float v = (m < NF) ? cospif(a) : sinpif(a);
    store_pair(bh, bl, idx, v);
}
__global__ void gen_basisB(__nv_bfloat16* ch, __nv_bfloat16* cl,
                           __nv_bfloat16* sh, __nv_bfloat16* sl) {
    int idx = blockIdx.x * 256 + threadIdx.x;
    if (idx >= MF * TOKP) return;
    int m = idx / TOKP, j = idx % TOKP;
    float cv = 0.f, sv = 0.f;
    if (j < TOK) {
        int rr = (m * j) % TOK;
        float a = 2.0f * (float)rr / (float)TOK;
        cv = cospif(a); sv = sinpif(a);
    }
    store_pair(ch, cl, idx, cv);
    store_pair(sh, sl, idx, sv);
}
__global__ void split_convw(const float* __restrict__ w,
                            __nv_bfloat16* h, __nv_bfloat16* l) {
    int idx = blockIdx.x * 256 + threadIdx.x;
    if (idx >= DIM * KPE) return;
    store_pair(h, l, idx, w[idx]);
}
__global__ void tsplit_w1(const float* __restrict__ w,
                          __nv_bfloat16* h, __nv_bfloat16* l) {
    int idx = blockIdx.x * 256 + threadIdx.x;
    if (idx >= LAYERS * HIDN * DIM) return;
    int l_ = idx / (HIDN * DIM);
    int rem = idx - l_ * HIDN * DIM;
    int n = rem / DIM, k = rem % DIM;
    store_pair(h, l, idx, w[(size_t)l_ * DIM * HIDN + (size_t)k * HIDN + n]);
}
__global__ void tsplit_w2(const float* __restrict__ w,
                          __nv_bfloat16* h, __nv_bfloat16* l) {
    int idx = blockIdx.x * 256 + threadIdx.x;
    if (idx >= LAYERS * DIM * HIDN) return;
    int l_ = idx / (DIM * HIDN);
    int rem = idx - l_ * DIM * HIDN;
    int n = rem / HIDN, k = rem % HIDN;
    store_pair(h, l, idx, w[(size_t)l_ * HIDN * DIM + (size_t)k * DIM + n]);
}
__global__ void zeropad_CS(__nv_bfloat16* a, __nv_bfloat16* b,
                           __nv_bfloat16* c, __nv_bfloat16* d) {
    int idx = blockIdx.x * 256 + threadIdx.x;
    const int PADC = TOKP - TOK;
    if (idx >= BNF * PADC) return;
    int rr = idx / PADC, cc = TOK + idx % PADC;
    size_t off = (size_t)rr * TOKP + cc;
    __nv_bfloat16 z = __float2bfloat16(0.f);
    a[off] = z; b[off] = z; c[off] = z; d[off] = z;
}
__global__ void im2col_pair(const float* __restrict__ x,
                            __nv_bfloat16* __restrict__ Xh, __nv_bfloat16* __restrict__ Xl) {
    size_t idx = (size_t)blockIdx.x * 256 + threadIdx.x;
    if (idx >= (size_t)BATCH * NPAT * KPE) return;
    int k = (int)(idx % KPE);
    size_t r = idx / KPE;
    int pr = (int)(r % NPAT);
    int b = (int)(r / NPAT);
    int gh = pr >> 5, gw = pr & 31;
    int c = k >> 8, rem = k & 255, p = rem >> 4, q = rem & 15;
    float v = x[(((size_t)(b * 3 + c) * 512) + gh * 16 + p) * 512 + gw * 16 + q];
    store_pair(Xh, Xl, idx, v);
}
__global__ void cls_kernel(const float* __restrict__ cls, const float* __restrict__ pos,
                           float* __restrict__ t) {
    int idx = blockIdx.x * 256 + threadIdx.x;
    if (idx >= BATCH * DIM) return;
    int b = idx >> 8, n = idx & 255;
    t[(size_t)b * TOK * DIM + n] = cls[n] + pos[n];
}
__global__ void ln_pair(const float* __restrict__ in,
                        __nv_bfloat16* __restrict__ oh, __nv_bfloat16* __restrict__ ol,
                        const float* __restrict__ s, const float* __restrict__ bb, int rows) {
    const int warp = threadIdx.x >> 5;
    const int lane = threadIdx.x & 31;
    const int row = blockIdx.x * 8 + warp;
    if (row >= rows) return;
    const float* p = in + (size_t)row * DIM;
    float v[8], sum = 0.f;
#pragma unroll
    for (int i = 0; i < 8; i++) { v[i] = p[lane + 32 * i]; sum += v[i]; }
#pragma unroll
    for (int o = 16; o; o >>= 1) sum += __shfl_xor_sync(0xffffffffu, sum, o);
    const float mean = sum * (1.f / 256.f);
    float var = 0.f;
#pragma unroll
    for (int i = 0; i < 8; i++) { float d = v[i] - mean; var += d * d; }
#pragma unroll
    for (int o = 16; o; o >>= 1) var += __shfl_xor_sync(0xffffffffu, var, o);
    const float rs = rsqrtf(var * (1.f / 256.f) + EPS);
    const size_t ro = (size_t)row * DIM;
#pragma unroll
    for (int i = 0; i < 8; i++) {
        int n = lane + 32 * i;
        store_pair(oh, ol, ro + n, (v[i] - mean) * rs * s[n] + bb[n]);
    }
}
__global__ void scatter_kernel(const float* __restrict__ U, const float* __restrict__ V,
                               float* __restrict__ t) {
    int idx = blockIdx.x * 256 + threadIdx.x;
    if (idx >= MF * BNF) return;
    int nf = idx % NF;
    int tmp = idx / NF;
    int b = tmp % BATCH;
    int m = tmp / BATCH;
    size_t uoff = (size_t)m * BNF + b * NF + nf;
    float u = U[uoff], v = V[uoff];
    float d1 = u - v, d2 = u + v;
    float* tb = t + (size_t)b * TOK * DIM;
    tb[m * DIM + nf] += d1;
    bool nmir = (nf >= 1 && nf <= 127);
    if (nmir) tb[m * DIM + (DIM - nf)] += d2;
    if (m >= 1) {
        int m2 = TOK - m;
        tb[m2 * DIM + nf] += d2;
        if (nmir) tb[m2 * DIM + (DIM - nf)] += d1;
    }
}
__global__ void pool_kernel(const float* __restrict__ t, float* __restrict__ pooled) {
    int b = blockIdx.x, n = threadIdx.x;
    const float* p = t + (size_t)b * TOK * DIM + n;
    float s0 = 0.f, s1 = 0.f, s2 = 0.f, s3 = 0.f;
    int j = 0;
    for (; j + 4 <= TOK; j += 4) {
        s0 += p[(size_t)(j + 0) * DIM];
        s1 += p[(size_t)(j + 1) * DIM];
        s2 += p[(size_t)(j + 2) * DIM];
        s3 += p[(size_t)(j + 3) * DIM];
    }
    for (; j < TOK; j++) s0 += p[(size_t)j * DIM];
    pooled[b * DIM + n] = (s0 + s1 + s2 + s3) * (1.0f / (float)TOK);
}
__global__ void head_kernel(const float* __restrict__ pooled,
                            const float* __restrict__ hs, const float* __restrict__ hb,
                            const float* __restrict__ W, const float* __restrict__ wb,
                            float* __restrict__ out) {
    __shared__ float sln[DIM];
    __shared__ float red[8];
    const int b = blockIdx.x, tid = threadIdx.x;
    const int lane = tid & 31, warp = tid >> 5;

    float x = pooled[b * DIM + tid];
    float sum = x;
#pragma unroll
    for (int o = 16; o; o >>= 1) sum += __shfl_xor_sync(0xffffffffu, sum, o);
    if (lane == 0) red[warp] = sum;
    __syncthreads();
    float mean;
    {
        float t0 = (lane < 8) ? red[lane] : 0.f;
#pragma unroll
        for (int o = 4; o; o >>= 1) t0 += __shfl_xor_sync(0xffffffffu, t0, o);
        mean = __shfl_sync(0xffffffffu, t0, 0) * (1.f / 256.f);
    }
    __syncthreads();
    float d = x - mean;
    float vv = d * d;
#pragma unroll
    for (int o = 16; o; o >>= 1) vv += __shfl_xor_sync(0xffffffffu, vv, o);
    if (lane == 0) red[warp] = vv;
    __syncthreads();
    float var;
    {
        float t0 = (lane < 8) ? red[lane] : 0.f;
#pragma unroll
        for (int o = 4; o; o >>= 1) t0 += __shfl_xor_sync(0xffffffffu, t0, o);
        var = __shfl_sync(0xffffffffu, t0, 0) * (1.f / 256.f);
    }
    float rs = rsqrtf(var + EPS);
    sln[tid] = d * rs * hs[tid] + hb[tid];
    __syncthreads();

    float lg[4];
#pragma unroll
    for (int jj = 0; jj < 4; jj++) {
        int n = tid + jj * 256;
        float a = 0.f;
        if (n < NC) {
            for (int k = 0; k < DIM; k++) a += sln[k] * W[(size_t)k * NC + n];
            a += wb[n];
        }
        lg[jj] = a;
    }
    float mx = -3.4e38f;
#pragma unroll
    for (int jj = 0; jj < 4; jj++) if (tid + jj * 256 < NC && lg[jj] > mx) mx = lg[jj];
#pragma unroll
    for (int o = 16; o; o >>= 1) mx = fmaxf(mx, __shfl_xor_sync(0xffffffffu, mx, o));
    __syncthreads();
    if (lane == 0) red[warp] = mx;
    __syncthreads();
    {
        float t0 = (lane < 8) ? red[lane] : -3.4e38f;
#pragma unroll
        for (int o = 4; o; o >>= 1) t0 = fmaxf(t0, __shfl_xor_sync(0xffffffffu, t0, o));
        mx = __shfl_sync(0xffffffffu, t0, 0);
    }
    float es = 0.f;
#pragma unroll
    for (int jj = 0; jj < 4; jj++) {
        int n = tid + jj * 256;
        if (n < NC) { lg[jj] = expf(lg[jj] - mx); es += lg[jj]; }
    }
#pragma unroll
    for (int o = 16; o; o >>= 1) es += __shfl_xor_sync(0xffffffffu, es, o);
    __syncthreads();
    if (lane == 0) red[warp] = es;
    __syncthreads();
    {
        float t0 = (lane < 8) ? red[lane] : 0.f;
#pragma unroll
        for (int o = 4; o; o >>= 1) t0 += __shfl_xor_sync(0xffffffffu, t0, o);
        es = __shfl_sync(0xffffffffu, t0, 0);
    }
    float inv = 1.f / es;
#pragma unroll
    for (int jj = 0; jj < 4; jj++) {
        int n = tid + jj * 256;
        if (n < NC) out[(size_t)b * NC + n] = lg[jj] * inv;
    }
}

// ------------------------------ launch ------------------------------------
static inline void run_mma(const __nv_bfloat16* Ah, const __nv_bfloat16* Al, int lda,
                           const __nv_bfloat16* Bh, const __nv_bfloat16* Bl, int ldb,
                           int M, int N, int K, int mode, int ldc,
                           const float* bias, const float* extra, float* outf,
                           __nv_bfloat16* o0 = nullptr, __nv_bfloat16* o1 = nullptr,
                           __nv_bfloat16* o2 = nullptr, __nv_bfloat16* o3 = nullptr)
{
    dim3 grid((N + 127) / 128, (M + 127) / 128);
    gemm_mma<<<grid, 256, SMEM_TOTAL>>>(Ah, Al, lda, Bh, Bl, ldb, M, N, K,
                                        mode, ldc, bias, extra, outf, o0, o1, o2, o3);
}

extern "C" void kernel_launch(void* const* d_in, const int* in_sizes, int n_in,
                              void* d_out, int out_size)
{
    const float* x       = (const float*)d_in[0];
    const float* conv_w  = (const float*)d_in[1];
    const float* conv_b  = (const float*)d_in[2];
    const float* pos_emb = (const float*)d_in[3];
    const float* cls_tok = (const float*)d_in[4];
    const float* ln1_s   = (const float*)d_in[5];
    const float* ln1_b   = (const float*)d_in[6];
    const float* ln2_s   = (const float*)d_in[7];
    const float* ln2_b   = (const float*)d_in[8];
    const float* w1      = (const float*)d_in[9];
    const float* b1      = (const float*)d_in[10];
    const float* w2      = (const float*)d_in[11];
    const float* b2      = (const float*)d_in[12];
    const float* h_ln_s  = (const float*)d_in[13];
    const float* h_ln_b  = (const float*)d_in[14];
    const float* head_w  = (const float*)d_in[15];
    const float* head_b  = (const float*)d_in[16];
    float* out = (float*)d_out;

    float *t, *U, *V, *pl;
    __nv_bfloat16 *hH, *hL, *XH, *XL, *hidH, *hidL;
    __nv_bfloat16 *CH, *CL, *SH, *SL;
    __nv_bfloat16 *cwH, *cwL, *bAH, *bAL, *cBH, *cBL, *sBH, *sBL;
    __nv_bfloat16 *w1H, *w1L, *w2H, *w2L;
    cudaGetSymbolAddress((void**)&t,    g_t);
    cudaGetSymbolAddress((void**)&U,    g_U);
    cudaGetSymbolAddress((void**)&V,    g_V);
    cudaGetSymbolAddress((void**)&pl,   g_pool);
    cudaGetSymbolAddress((void**)&hH,   g_hH);
    cudaGetSymbolAddress((void**)&hL,   g_hL);
    cudaGetSymbolAddress((void**)&XH,   g_XH);
    cudaGetSymbolAddress((void**)&XL,   g_XL);
    cudaGetSymbolAddress((void**)&hidH, g_hidH);
    cudaGetSymbolAddress((void**)&hidL, g_hidL);
    cudaGetSymbolAddress((void**)&CH,   g_CH);
    cudaGetSymbolAddress((void**)&CL,   g_CL);
    cudaGetSymbolAddress((void**)&SH,   g_SH);
    cudaGetSymbolAddress((void**)&SL,   g_SL);
    cudaGetSymbolAddress((void**)&cwH,  g_cwH);
    cudaGetSymbolAddress((void**)&cwL,  g_cwL);
    cudaGetSymbolAddress((void**)&bAH,  g_bAH);
    cudaGetSymbolAddress((void**)&bAL,  g_bAL);
    cudaGetSymbolAddress((void**)&cBH,  g_cBH);
    cudaGetSymbolAddress((void**)&cBL,  g_cBL);
    cudaGetSymbolAddress((void**)&sBH,  g_sBH);
    cudaGetSymbolAddress((void**)&sBL,  g_sBL);
    cudaGetSymbolAddress((void**)&w1H,  g_w1H);
    cudaGetSymbolAddress((void**)&w1L,  g_w1L);
    cudaGetSymbolAddress((void**)&w2H,  g_w2H);
    cudaGetSymbolAddress((void**)&w2L,  g_w2L);

    cudaFuncSetAttribute(gemm_mma, cudaFuncAttributeMaxDynamicSharedMemorySize, SMEM_TOTAL);

    // ---- prep ----
    gen_basisA<<<(258 * DIM + 255) / 256, 256>>>(bAH, bAL);
    gen_basisB<<<(MF * TOKP + 255) / 256, 256>>>(cBH, cBL, sBH, sBL);
    split_convw<<<(DIM * KPE + 255) / 256, 256>>>(conv_w, cwH, cwL);
    tsplit_w1<<<(LAYERS * HIDN * DIM + 255) / 256, 256>>>(w1, w1H, w1L);
    tsplit_w2<<<(LAYERS * DIM * HIDN + 255) / 256, 256>>>(w2, w2H, w2L);
    zeropad_CS<<<(BNF * (TOKP - TOK) + 255) / 256, 256>>>(CH, CL, SH, SL);

    // ---- patch embed ----
    im2col_pair<<<(int)(((size_t)BATCH * NPAT * KPE + 255) / 256), 256>>>(x, XH, XL);
    run_mma(XH, XL, KPE, cwH, cwL, KPE, BATCH * NPAT, DIM, KPE,
            M_PATCH, 0, conv_b, pos_emb, t);
    cls_kernel<<<(BATCH * DIM + 255) / 256, 256>>>(cls_tok, pos_emb, t);

    for (int i = 0; i < LAYERS; i++) {
        // --- FNet mixing ---
        ln_pair<<<(ROWS + 7) / 8, 256>>>(t, hH, hL, ln1_s + i * DIM, ln1_b + i * DIM, ROWS);
        // stage 1: [cos;sin](258,256) @ h(65600,256)^T -> C/S pairs [b*NF+nf][j]
        run_mma(bAH, bAL, DIM, hH, hL, DIM, 258, ROWS, DIM,
                M_DFT1, 0, nullptr, nullptr, nullptr, CH, CL, SH, SL);
        // stage 2: U = cB(513,1088) @ C^T ; V = sB @ S^T
        run_mma(cBH, cBL, TOKP, CH, CL, TOKP, MF, BNF, TOKP, M_F32, BNF,
                nullptr, nullptr, U);
        run_mma(sBH, sBL, TOKP, SH, SL, TOKP, MF, BNF, TOKP, M_F32, BNF,
                nullptr, nullptr, V);
        scatter_kernel<<<(MF * BNF + 255) / 256, 256>>>(U, V, t);

        // --- FFN ---
        ln_pair<<<(ROWS + 7) / 8, 256>>>(t, hH, hL, ln2_s + i * DIM, ln2_b + i * DIM, ROWS);
        run_mma(hH, hL, DIM, w1H + (size_t)i * HIDN * DIM, w1L + (size_t)i * HIDN * DIM, DIM,
                ROWS, HIDN, DIM, M_FFN1, HIDN, b1 + i * HIDN, nullptr, nullptr, hidH, hidL);
        run_mma(hidH, hidL, HIDN, w2H + (size_t)i * DIM * HIDN, w2L + (size_t)i * DIM * HIDN, HIDN,
                ROWS, DIM, HIDN, M_FFN2, DIM, b2 + i * DIM, nullptr, t);
    }

    pool_kernel<<<BATCH, DIM>>>(t, pl);
    head_kernel<<<BATCH, DIM>>>(pl, h_ln_s, h_ln_b, head_w, head_b, out);
}

// round 7
// speedup vs baseline: 2.6678x; 1.7095x over previous
#include <cuda_runtime.h>
#include <cuda_bf16.h>
#include <cstdint>

// ---------------------------------------------------------------------------
// VFNet: all GEMMs as bf16x3 split-precision warp-level mma.sync (HMMA).
// 128x256x32 CTA tile, 512 threads (16 warps), 4-stage cp.async pipeline,
// XOR-swizzled 64B smem rows. Fused epilogues; DFT via half-spectrum GEMMs.
// ---------------------------------------------------------------------------

#define BATCH 64
#define TOK   1025
#define DIM   256
#define HIDN  1024
#define LAYERS 6
#define NC    1000
#define NF    129
#define MF    513
#define ROWS  (BATCH*TOK)       // 65600
#define NPAT  1024
#define KPE   768
#define TOKP  1088
#define BNF   (BATCH*NF)        // 8256
#define EPS   1e-5f

// ------------------------------ scratch -----------------------------------
__device__ __align__(128) float          g_t   [ROWS*DIM];
__device__ __align__(128) __nv_bfloat16  g_hH  [ROWS*DIM];
__device__ __align__(128) __nv_bfloat16  g_hL  [ROWS*DIM];
__device__ __align__(128) __nv_bfloat16  g_XH  [BATCH*NPAT*KPE];
__device__ __align__(128) __nv_bfloat16  g_XL  [BATCH*NPAT*KPE];
__device__ __align__(128) __nv_bfloat16  g_hidH[ROWS*HIDN];
__device__ __align__(128) __nv_bfloat16  g_hidL[ROWS*HIDN];
__device__ __align__(128) __nv_bfloat16  g_CH  [BNF*TOKP];
__device__ __align__(128) __nv_bfloat16  g_CL  [BNF*TOKP];
__device__ __align__(128) __nv_bfloat16  g_SH  [BNF*TOKP];
__device__ __align__(128) __nv_bfloat16  g_SL  [BNF*TOKP];
__device__ __align__(128) float          g_U   [MF*BNF];
__device__ __align__(128) float          g_V   [MF*BNF];
__device__ __align__(128) __nv_bfloat16  g_cwH [DIM*KPE],  g_cwL [DIM*KPE];
__device__ __align__(128) __nv_bfloat16  g_bAH [258*DIM],  g_bAL [258*DIM];
__device__ __align__(128) __nv_bfloat16  g_cBH [MF*TOKP],  g_cBL [MF*TOKP];
__device__ __align__(128) __nv_bfloat16  g_sBH [MF*TOKP],  g_sBL [MF*TOKP];
__device__ __align__(128) __nv_bfloat16  g_w1H [LAYERS*HIDN*DIM], g_w1L [LAYERS*HIDN*DIM];
__device__ __align__(128) __nv_bfloat16  g_w2H [LAYERS*DIM*HIDN], g_w2L [LAYERS*DIM*HIDN];
__device__ __align__(128) float          g_pool[BATCH*DIM];

// --------------------------- PTX helpers -----------------------------------
__device__ __forceinline__ uint32_t smem_u32(const void* p) {
    uint32_t a;
    asm("{ .reg .u64 t; cvta.to.shared.u64 t, %1; cvt.u32.u64 %0, t; }" : "=r"(a) : "l"(p));
    return a;
}
__device__ __forceinline__ void cp16(uint32_t dst, const void* src, bool v) {
    asm volatile("cp.async.cg.shared.global [%0], [%1], 16, %2;"
                 :: "r"(dst), "l"(src), "r"(v ? 16 : 0) : "memory");
}
#define CP_COMMIT() asm volatile("cp.async.commit_group;" ::: "memory")
#define CP_WAIT(n)  asm volatile("cp.async.wait_group %0;" :: "n"(n) : "memory")

#define LDSM4(r, addr) \
    asm volatile("ldmatrix.sync.aligned.m8n8.x4.shared.b16 {%0,%1,%2,%3}, [%4];" \
                 : "=r"((r)[0]), "=r"((r)[1]), "=r"((r)[2]), "=r"((r)[3]) : "r"(addr))

#define MMA(c, a, b0, b1) \
    asm volatile("mma.sync.aligned.m16n8k16.row.col.f32.bf16.bf16.f32 " \
                 "{%0,%1,%2,%3}, {%4,%5,%6,%7}, {%8,%9}, {%0,%1,%2,%3};" \
                 : "+f"((c)[0]), "+f"((c)[1]), "+f"((c)[2]), "+f"((c)[3]) \
                 : "r"((a)[0]), "r"((a)[1]), "r"((a)[2]), "r"((a)[3]), \
                   "r"(b0), "r"(b1))

// SMEM stage: Ah(128x64B) Al Bh(256x64B) Bl, XOR-swizzled rows.
#define A_BYTES 8192
#define B_BYTES 16384
#define STAGEB  (2*A_BYTES + 2*B_BYTES)   // 49152
#define NSTAGE  4
#define SMEM_TOTAL (NSTAGE*STAGEB)        // 196608

// swizzled offset within one matrix: row has 4 16B chunks
__device__ __forceinline__ uint32_t swz(int row, int c) {
    return (uint32_t)(row * 64 + ((c ^ ((row >> 1) & 3)) << 4));
}

// epilogue modes
#define M_PATCH 0
#define M_DFT1  1
#define M_F32   2
#define M_FFN1  3
#define M_FFN2  4

// --------------------------- mma.sync GEMM ---------------------------------
__global__ __launch_bounds__(512, 1) void gemm_mma(
    const __nv_bfloat16* __restrict__ Ah, const __nv_bfloat16* __restrict__ Al, int lda,
    const __nv_bfloat16* __restrict__ Bh, const __nv_bfloat16* __restrict__ Bl, int ldb,
    int M, int Nvalid, int K, int mode, int ldc,
    const float* __restrict__ bias, const float* __restrict__ extra,
    float* __restrict__ outf,
    __nv_bfloat16* __restrict__ o0, __nv_bfloat16* __restrict__ o1,
    __nv_bfloat16* __restrict__ o2, __nv_bfloat16* __restrict__ o3)
{
    extern __shared__ char smc[];
    const uint32_t sb = smem_u32(smc);
    const int tid  = threadIdx.x;
    const int lane = tid & 31;
    const int wid  = tid >> 5;
    const int wm   = wid & 3;      // 4 warps along M (32 rows each)
    const int wn   = wid >> 2;     // 4 warps along N (64 cols each)
    const int mBase = blockIdx.y * 128;
    const int nBase = blockIdx.x * 256;

    const int NCH = K >> 5;

    const int lrow = tid >> 2;     // loader row within 128 (A) / half-B
    const int lchk = tid & 3;

    auto load_stage = [&](int c) {
        const int k0 = c << 5;
        const uint32_t stg = sb + (uint32_t)(c & (NSTAGE - 1)) * STAGEB;
        // t=0: Ah, t=1: Al
        {
            const int gm = mBase + lrow;
            const bool ok = gm < M;
            const size_t ro = (size_t)(ok ? gm : 0) * lda + k0 + lchk * 8;
            const uint32_t d = stg + swz(lrow, lchk);
            cp16(d,            Ah + ro, ok);
            cp16(d + A_BYTES,  Al + ro, ok);
        }
        // t=2..5: Bh rows 0-127,128-255; Bl rows 0-127,128-255
        {
            const uint32_t bbase = stg + 2 * A_BYTES;
#pragma unroll
            for (int half = 0; half < 2; half++) {
                const int row = lrow + half * 128;
                const int gn = nBase + row;
                const bool ok = gn < Nvalid;
                const size_t ro = (size_t)(ok ? gn : 0) * ldb + k0 + lchk * 8;
                const uint32_t d = bbase + swz(row, lchk);
                cp16(d,            Bh + ro, ok);
                cp16(d + B_BYTES,  Bl + ro, ok);
            }
        }
    };

    float acc[2][8][4];
#pragma unroll
    for (int mt = 0; mt < 2; mt++)
#pragma unroll
        for (int nt = 0; nt < 8; nt++)
#pragma unroll
            for (int e = 0; e < 4; e++) acc[mt][nt][e] = 0.f;

    for (int c = 0; c < NSTAGE - 1 && c < NCH; c++) { load_stage(c); CP_COMMIT(); }

    for (int c = 0; c < NCH; c++) {
        if (c + NSTAGE - 1 < NCH) { load_stage(c + NSTAGE - 1); CP_COMMIT(); }
        {
            int ahead = NCH - 1 - c;
            if (ahead > NSTAGE - 1) ahead = NSTAGE - 1;
            if (ahead >= 3)      CP_WAIT(3);
            else if (ahead == 2) CP_WAIT(2);
            else if (ahead == 1) CP_WAIT(1);
            else                 CP_WAIT(0);
        }
        __syncthreads();

        const uint32_t stg = sb + (uint32_t)(c & (NSTAGE - 1)) * STAGEB;
        const uint32_t baB = stg + 2 * A_BYTES;

#pragma unroll
        for (int ks = 0; ks < 2; ks++) {
            uint32_t aH[2][4], aL[2][4];
#pragma unroll
            for (int mt = 0; mt < 2; mt++) {
                const int row = wm * 32 + mt * 16 + (lane & 15);
                const int chk = ks * 2 + (lane >> 4);
                const uint32_t ad = stg + swz(row, chk);
                LDSM4(aH[mt], ad);
                LDSM4(aL[mt], ad + A_BYTES);
            }
#pragma unroll
            for (int nt2 = 0; nt2 < 4; nt2++) {
                const int row = wn * 64 + nt2 * 16 + ((lane >> 4) << 3) + (lane & 7);
                const int chk = ks * 2 + ((lane >> 3) & 1);
                const uint32_t ad = baB + swz(row, chk);
                uint32_t bH[4], bL[4];
                LDSM4(bH, ad);
                LDSM4(bL, ad + B_BYTES);
#pragma unroll
                for (int h = 0; h < 2; h++) {
                    const int nt = nt2 * 2 + h;
#pragma unroll
                    for (int mt = 0; mt < 2; mt++) {
                        MMA(acc[mt][nt], aH[mt], bH[h * 2], bH[h * 2 + 1]);
                        MMA(acc[mt][nt], aH[mt], bL[h * 2], bL[h * 2 + 1]);
                        MMA(acc[mt][nt], aL[mt], bH[h * 2], bH[h * 2 + 1]);
                    }
                }
            }
        }
        __syncthreads();
    }

    // ------------------------------ epilogue -------------------------------
#pragma unroll
    for (int mt = 0; mt < 2; mt++) {
#pragma unroll
        for (int nt = 0; nt < 8; nt++) {
#pragma unroll
            for (int e = 0; e < 4; e++) {
                const int gm = mBase + wm * 32 + mt * 16 + (lane >> 2) + ((e >> 1) << 3);
                const int n  = nBase + wn * 64 + nt * 8 + ((lane & 3) << 1) + (e & 1);
                if (gm >= M || n >= Nvalid) continue;
                const float val = acc[mt][nt][e];
                if (mode == M_PATCH) {
                    const int b = gm >> 10, p = gm & 1023;
                    outf[((size_t)(b * TOK + p + 1)) * DIM + n] =
                        val + bias[n] + extra[(size_t)(p + 1) * DIM + n];
                } else if (mode == M_DFT1) {
                    const bool isCos = (gm < NF);
                    const int nf = isCos ? gm : gm - NF;
                    const int b = n / TOK;
                    const int j = n - b * TOK;
                    const size_t off = ((size_t)(b * NF + nf)) * TOKP + j;
                    const __nv_bfloat16 hi = __float2bfloat16(val);
                    if (isCos) { o0[off] = hi; o1[off] = __float2bfloat16(val - __bfloat162float(hi)); }
                    else       { o2[off] = hi; o3[off] = __float2bfloat16(val - __bfloat162float(hi)); }
                } else if (mode == M_F32) {
                    outf[(size_t)gm * ldc + n] = val;
                } else if (mode == M_FFN1) {
                    float v = val + bias[n];
                    v = v > 0.f ? v : 0.01f * v;
                    const size_t off = (size_t)gm * ldc + n;
                    const __nv_bfloat16 hi = __float2bfloat16(v);
                    o0[off] = hi;
                    o1[off] = __float2bfloat16(v - __bfloat162float(hi));
                } else { // M_FFN2
                    const size_t off = (size_t)gm * ldc + n;
                    outf[off] = outf[off] + val + bias[n];
                }
            }
        }
    }
}

// ------------------------------ prep kernels --------------------------------
__device__ __forceinline__ void store_pair(__nv_bfloat16* h, __nv_bfloat16* l,
                                           size_t i, float v) {
    const __nv_bfloat16 hi = __float2bfloat16(v);
    h[i] = hi;
    l[i] = __float2bfloat16(v - __bfloat162float(hi));
}

__global__ void gen_basisA(__nv_bfloat16* bh, __nv_bfloat16* bl) {
    int idx = blockIdx.x * 256 + threadIdx.x;
    if (idx >= 258 * DIM) return;
    int m = idx / DIM, k = idx % DIM;
    int nf = (m < NF) ? m : m - NF;
    int rr = (k * nf) & 255;
    float a = 2.0f * (float)rr / 256.0f;
    float v = (m < NF) ? cospif(a) : sinpif(a);
    store_pair(bh, bl, idx, v);
}
__global__ void gen_basisB(__nv_bfloat16* ch, __nv_bfloat16* cl,
                           __nv_bfloat16* sh, __nv_bfloat16* sl) {
    int idx = blockIdx.x * 256 + threadIdx.x;
    if (idx >= MF * TOKP) return;
    int m = idx / TOKP, j = idx % TOKP;
    float cv = 0.f, sv = 0.f;
    if (j < TOK) {
        int rr = (m * j) % TOK;
        float a = 2.0f * (float)rr / (float)TOK;
        cv = cospif(a); sv = sinpif(a);
    }
    store_pair(ch, cl, idx, cv);
    store_pair(sh, sl, idx, sv);
}
__global__ void split_convw(const float* __restrict__ w,
                            __nv_bfloat16* h, __nv_bfloat16* l) {
    int idx = blockIdx.x * 256 + threadIdx.x;
    if (idx >= DIM * KPE) return;
    store_pair(h, l, idx, w[idx]);
}
__global__ void tsplit_w1(const float* __restrict__ w,
                          __nv_bfloat16* h, __nv_bfloat16* l) {
    int idx = blockIdx.x * 256 + threadIdx.x;
    if (idx >= LAYERS * HIDN * DIM) return;
    int l_ = idx / (HIDN * DIM);
    int rem = idx - l_ * HIDN * DIM;
    int n = rem / DIM, k = rem % DIM;
    store_pair(h, l, idx, w[(size_t)l_ * DIM * HIDN + (size_t)k * HIDN + n]);
}
__global__ void tsplit_w2(const float* __restrict__ w,
                          __nv_bfloat16* h, __nv_bfloat16* l) {
    int idx = blockIdx.x * 256 + threadIdx.x;
    if (idx >= LAYERS * DIM * HIDN) return;
    int l_ = idx / (DIM * HIDN);
    int rem = idx - l_ * DIM * HIDN;
    int n = rem / HIDN, k = rem % HIDN;
    store_pair(h, l, idx, w[(size_t)l_ * HIDN * DIM + (size_t)k * DIM + n]);
}
__global__ void zeropad_CS(__nv_bfloat16* a, __nv_bfloat16* b,
                           __nv_bfloat16* c, __nv_bfloat16* d) {
    int idx = blockIdx.x * 256 + threadIdx.x;
    const int PADC = TOKP - TOK;
    if (idx >= BNF * PADC) return;
    int rr = idx / PADC, cc = TOK + idx % PADC;
    size_t off = (size_t)rr * TOKP + cc;
    __nv_bfloat16 z = __float2bfloat16(0.f);
    a[off] = z; b[off] = z; c[off] = z; d[off] = z;
}
__global__ void im2col_pair(const float* __restrict__ x,
                            __nv_bfloat16* __restrict__ Xh, __nv_bfloat16* __restrict__ Xl) {
    size_t idx = (size_t)blockIdx.x * 256 + threadIdx.x;
    if (idx >= (size_t)BATCH * NPAT * KPE) return;
    int k = (int)(idx % KPE);
    size_t r = idx / KPE;
    int pr = (int)(r % NPAT);
    int b = (int)(r / NPAT);
    int gh = pr >> 5, gw = pr & 31;
    int c = k >> 8, rem = k & 255, p = rem >> 4, q = rem & 15;
    float v = x[(((size_t)(b * 3 + c) * 512) + gh * 16 + p) * 512 + gw * 16 + q];
    store_pair(Xh, Xl, idx, v);
}
__global__ void cls_kernel(const float* __restrict__ cls, const float* __restrict__ pos,
                           float* __restrict__ t) {
    int idx = blockIdx.x * 256 + threadIdx.x;
    if (idx >= BATCH * DIM) return;
    int b = idx >> 8, n = idx & 255;
    t[(size_t)b * TOK * DIM + n] = cls[n] + pos[n];
}
__global__ void ln_pair(const float* __restrict__ in,
                        __nv_bfloat16* __restrict__ oh, __nv_bfloat16* __restrict__ ol,
                        const float* __restrict__ s, const float* __restrict__ bb, int rows) {
    const int warp = threadIdx.x >> 5;
    const int lane = threadIdx.x & 31;
    const int row = blockIdx.x * 8 + warp;
    if (row >= rows) return;
    const float* p = in + (size_t)row * DIM;
    float v[8], sum = 0.f;
#pragma unroll
    for (int i = 0; i < 8; i++) { v[i] = p[lane + 32 * i]; sum += v[i]; }
#pragma unroll
    for (int o = 16; o; o >>= 1) sum += __shfl_xor_sync(0xffffffffu, sum, o);
    const float mean = sum * (1.f / 256.f);
    float var = 0.f;
#pragma unroll
    for (int i = 0; i < 8; i++) { float d = v[i] - mean; var += d * d; }
#pragma unroll
    for (int o = 16; o; o >>= 1) var += __shfl_xor_sync(0xffffffffu, var, o);
    const float rs = rsqrtf(var * (1.f / 256.f) + EPS);
    const size_t ro = (size_t)row * DIM;
#pragma unroll
    for (int i = 0; i < 8; i++) {
        int n = lane + 32 * i;
        store_pair(oh, ol, ro + n, (v[i] - mean) * rs * s[n] + bb[n]);
    }
}
__global__ void scatter_kernel(const float* __restrict__ U, const float* __restrict__ V,
                               float* __restrict__ t) {
    int idx = blockIdx.x * 256 + threadIdx.x;
    if (idx >= MF * BNF) return;
    int nf = idx % NF;
    int tmp = idx / NF;
    int b = tmp % BATCH;
    int m = tmp / BATCH;
    size_t uoff = (size_t)m * BNF + b * NF + nf;
    float u = U[uoff], v = V[uoff];
    float d1 = u - v, d2 = u + v;
    float* tb = t + (size_t)b * TOK * DIM;
    tb[m * DIM + nf] += d1;
    bool nmir = (nf >= 1 && nf <= 127);
    if (nmir) tb[m * DIM + (DIM - nf)] += d2;
    if (m >= 1) {
        int m2 = TOK - m;
        tb[m2 * DIM + nf] += d2;
        if (nmir) tb[m2 * DIM + (DIM - nf)] += d1;
    }
}
__global__ void pool_kernel(const float* __restrict__ t, float* __restrict__ pooled) {
    int b = blockIdx.x, n = threadIdx.x;
    const float* p = t + (size_t)b * TOK * DIM + n;
    float s0 = 0.f, s1 = 0.f, s2 = 0.f, s3 = 0.f;
    int j = 0;
    for (; j + 4 <= TOK; j += 4) {
        s0 += p[(size_t)(j + 0) * DIM];
        s1 += p[(size_t)(j + 1) * DIM];
        s2 += p[(size_t)(j + 2) * DIM];
        s3 += p[(size_t)(j + 3) * DIM];
    }
    for (; j < TOK; j++) s0 += p[(size_t)j * DIM];
    pooled[b * DIM + n] = (s0 + s1 + s2 + s3) * (1.0f / (float)TOK);
}
__global__ void head_kernel(const float* __restrict__ pooled,
                            const float* __restrict__ hs, const float* __restrict__ hb,
                            const float* __restrict__ W, const float* __restrict__ wb,
                            float* __restrict__ out) {
    __shared__ float sln[DIM];
    __shared__ float red[8];
    const int b = blockIdx.x, tid = threadIdx.x;
    const int lane = tid & 31, warp = tid >> 5;

    float x = pooled[b * DIM + tid];
    float sum = x;
#pragma unroll
    for (int o = 16; o; o >>= 1) sum += __shfl_xor_sync(0xffffffffu, sum, o);
    if (lane == 0) red[warp] = sum;
    __syncthreads();
    float mean;
    {
        float t0 = (lane < 8) ? red[lane] : 0.f;
#pragma unroll
        for (int o = 4; o; o >>= 1) t0 += __shfl_xor_sync(0xffffffffu, t0, o);
        mean = __shfl_sync(0xffffffffu, t0, 0) * (1.f / 256.f);
    }
    __syncthreads();
    float d = x - mean;
    float vv = d * d;
#pragma unroll
    for (int o = 16; o; o >>= 1) vv += __shfl_xor_sync(0xffffffffu, vv, o);
    if (lane == 0) red[warp] = vv;
    __syncthreads();
    float var;
    {
        float t0 = (lane < 8) ? red[lane] : 0.f;
#pragma unroll
        for (int o = 4; o; o >>= 1) t0 += __shfl_xor_sync(0xffffffffu, t0, o);
        var = __shfl_sync(0xffffffffu, t0, 0) * (1.f / 256.f);
    }
    float rs = rsqrtf(var + EPS);
    sln[tid] = d * rs * hs[tid] + hb[tid];
    __syncthreads();

    float lg[4];
#pragma unroll
    for (int jj = 0; jj < 4; jj++) {
        int n = tid + jj * 256;
        float a = 0.f;
        if (n < NC) {
            for (int k = 0; k < DIM; k++) a += sln[k] * W[(size_t)k * NC + n];
            a += wb[n];
        }
        lg[jj] = a;
    }
    float mx = -3.4e38f;
#pragma unroll
    for (int jj = 0; jj < 4; jj++) if (tid + jj * 256 < NC && lg[jj] > mx) mx = lg[jj];
#pragma unroll
    for (int o = 16; o; o >>= 1) mx = fmaxf(mx, __shfl_xor_sync(0xffffffffu, mx, o));
    __syncthreads();
    if (lane == 0) red[warp] = mx;
    __syncthreads();
    {
        float t0 = (lane < 8) ? red[lane] : -3.4e38f;
#pragma unroll
        for (int o = 4; o; o >>= 1) t0 = fmaxf(t0, __shfl_xor_sync(0xffffffffu, t0, o));
        mx = __shfl_sync(0xffffffffu, t0, 0);
    }
    float es = 0.f;
#pragma unroll
    for (int jj = 0; jj < 4; jj++) {
        int n = tid + jj * 256;
        if (n < NC) { lg[jj] = expf(lg[jj] - mx); es += lg[jj]; }
    }
#pragma unroll
    for (int o = 16; o; o >>= 1) es += __shfl_xor_sync(0xffffffffu, es, o);
    __syncthreads();
    if (lane == 0) red[warp] = es;
    __syncthreads();
    {
        float t0 = (lane < 8) ? red[lane] : 0.f;
#pragma unroll
        for (int o = 4; o; o >>= 1) t0 += __shfl_xor_sync(0xffffffffu, t0, o);
        es = __shfl_sync(0xffffffffu, t0, 0);
    }
    float inv = 1.f / es;
#pragma unroll
    for (int jj = 0; jj < 4; jj++) {
        int n = tid + jj * 256;
        if (n < NC) out[(size_t)b * NC + n] = lg[jj] * inv;
    }
}

// ------------------------------ launch ------------------------------------
static inline void run_mma(const __nv_bfloat16* Ah, const __nv_bfloat16* Al, int lda,
                           const __nv_bfloat16* Bh, const __nv_bfloat16* Bl, int ldb,
                           int M, int N, int K, int mode, int ldc,
                           const float* bias, const float* extra, float* outf,
                           __nv_bfloat16* o0 = nullptr, __nv_bfloat16* o1 = nullptr,
                           __nv_bfloat16* o2 = nullptr, __nv_bfloat16* o3 = nullptr)
{
    dim3 grid((N + 255) / 256, (M + 127) / 128);
    gemm_mma<<<grid, 512, SMEM_TOTAL>>>(Ah, Al, lda, Bh, Bl, ldb, M, N, K,
                                        mode, ldc, bias, extra, outf, o0, o1, o2, o3);
}

extern "C" void kernel_launch(void* const* d_in, const int* in_sizes, int n_in,
                              void* d_out, int out_size)
{
    const float* x       = (const float*)d_in[0];
    const float* conv_w  = (const float*)d_in[1];
    const float* conv_b  = (const float*)d_in[2];
    const float* pos_emb = (const float*)d_in[3];
    const float* cls_tok = (const float*)d_in[4];
    const float* ln1_s   = (const float*)d_in[5];
    const float* ln1_b   = (const float*)d_in[6];
    const float* ln2_s   = (const float*)d_in[7];
    const float* ln2_b   = (const float*)d_in[8];
    const float* w1      = (const float*)d_in[9];
    const float* b1      = (const float*)d_in[10];
    const float* w2      = (const float*)d_in[11];
    const float* b2      = (const float*)d_in[12];
    const float* h_ln_s  = (const float*)d_in[13];
    const float* h_ln_b  = (const float*)d_in[14];
    const float* head_w  = (const float*)d_in[15];
    const float* head_b  = (const float*)d_in[16];
    float* out = (float*)d_out;

    float *t, *U, *V, *pl;
    __nv_bfloat16 *hH, *hL, *XH, *XL, *hidH, *hidL;
    __nv_bfloat16 *CH, *CL, *SH, *SL;
    __nv_bfloat16 *cwH, *cwL, *bAH, *bAL, *cBH, *cBL, *sBH, *sBL;
    __nv_bfloat16 *w1H, *w1L, *w2H, *w2L;
    cudaGetSymbolAddress((void**)&t,    g_t);
    cudaGetSymbolAddress((void**)&U,    g_U);
    cudaGetSymbolAddress((void**)&V,    g_V);
    cudaGetSymbolAddress((void**)&pl,   g_pool);
    cudaGetSymbolAddress((void**)&hH,   g_hH);
    cudaGetSymbolAddress((void**)&hL,   g_hL);
    cudaGetSymbolAddress((void**)&XH,   g_XH);
    cudaGetSymbolAddress((void**)&XL,   g_XL);
    cudaGetSymbolAddress((void**)&hidH, g_hidH);
    cudaGetSymbolAddress((void**)&hidL, g_hidL);
    cudaGetSymbolAddress((void**)&CH,   g_CH);
    cudaGetSymbolAddress((void**)&CL,   g_CL);
    cudaGetSymbolAddress((void**)&SH,   g_SH);
    cudaGetSymbolAddress((void**)&SL,   g_SL);
    cudaGetSymbolAddress((void**)&cwH,  g_cwH);
    cudaGetSymbolAddress((void**)&cwL,  g_cwL);
    cudaGetSymbolAddress((void**)&bAH,  g_bAH);
    cudaGetSymbolAddress((void**)&bAL,  g_bAL);
    cudaGetSymbolAddress((void**)&cBH,  g_cBH);
    cudaGetSymbolAddress((void**)&cBL,  g_cBL);
    cudaGetSymbolAddress((void**)&sBH,  g_sBH);
    cudaGetSymbolAddress((void**)&sBL,  g_sBL);
    cudaGetSymbolAddress((void**)&w1H,  g_w1H);
    cudaGetSymbolAddress((void**)&w1L,  g_w1L);
    cudaGetSymbolAddress((void**)&w2H,  g_w2H);
    cudaGetSymbolAddress((void**)&w2L,  g_w2L);

    cudaFuncSetAttribute(gemm_mma, cudaFuncAttributeMaxDynamicSharedMemorySize, SMEM_TOTAL);

    // ---- order chosen so ncu (-s 5 -c 1) profiles the patch GEMM ----
    gen_basisA<<<(258 * DIM + 255) / 256, 256>>>(bAH, bAL);                       // 0
    gen_basisB<<<(MF * TOKP + 255) / 256, 256>>>(cBH, cBL, sBH, sBL);             // 1
    split_convw<<<(DIM * KPE + 255) / 256, 256>>>(conv_w, cwH, cwL);              // 2
    im2col_pair<<<(int)(((size_t)BATCH * NPAT * KPE + 255) / 256), 256>>>(x, XH, XL); // 3
    cls_kernel<<<(BATCH * DIM + 255) / 256, 256>>>(cls_tok, pos_emb, t);          // 4
    run_mma(XH, XL, KPE, cwH, cwL, KPE, BATCH * NPAT, DIM, KPE,                   // 5 <- profiled
            M_PATCH, 0, conv_b, pos_emb, t);
    tsplit_w1<<<(LAYERS * HIDN * DIM + 255) / 256, 256>>>(w1, w1H, w1L);
    tsplit_w2<<<(LAYERS * DIM * HIDN + 255) / 256, 256>>>(w2, w2H, w2L);
    zeropad_CS<<<(BNF * (TOKP - TOK) + 255) / 256, 256>>>(CH, CL, SH, SL);

    for (int i = 0; i < LAYERS; i++) {
        // --- FNet mixing ---
        ln_pair<<<(ROWS + 7) / 8, 256>>>(t, hH, hL, ln1_s + i * DIM, ln1_b + i * DIM, ROWS);
        run_mma(bAH, bAL, DIM, hH, hL, DIM, 258, ROWS, DIM,
                M_DFT1, 0, nullptr, nullptr, nullptr, CH, CL, SH, SL);
        run_mma(cBH, cBL, TOKP, CH, CL, TOKP, MF, BNF, TOKP, M_F32, BNF,
                nullptr, nullptr, U);
        run_mma(sBH, sBL, TOKP, SH, SL, TOKP, MF, BNF, TOKP, M_F32, BNF,
                nullptr, nullptr, V);
        scatter_kernel<<<(MF * BNF + 255) / 256, 256>>>(U, V, t);

        // --- FFN ---
        ln_pair<<<(ROWS + 7) / 8, 256>>>(t, hH, hL, ln2_s + i * DIM, ln2_b + i * DIM, ROWS);
        run_mma(hH, hL, DIM, w1H + (size_t)i * HIDN * DIM, w1L + (size_t)i * HIDN * DIM, DIM,
                ROWS, HIDN, DIM, M_FFN1, HIDN, b1 + i * HIDN, nullptr, nullptr, hidH, hidL);
        run_mma(hidH, hidL, HIDN, w2H + (size_t)i * DIM * HIDN, w2L + (size_t)i * DIM * HIDN, HIDN,
                ROWS, DIM, HIDN, M_FFN2, DIM, b2 + i * DIM, nullptr, t);
    }

    pool_kernel<<<BATCH, DIM>>>(t, pl);
    head_kernel<<<BATCH, DIM>>>(pl, h_ln_s, h_ln_b, head_w, head_b, out);
}

// round 10
// speedup vs baseline: 2.7811x; 1.0425x over previous
#include <cuda_runtime.h>
#include <cuda_bf16.h>
#include <cstdint>

// ---------------------------------------------------------------------------
// VFNet: all GEMMs as bf16x3 split-precision warp-level mma.sync (HMMA).
// 128x256x32 CTA tile, 512 threads (16 warps), 4-stage cp.async pipeline,
// single-barrier mainloop, register double-buffered B fragments.
// ---------------------------------------------------------------------------

#define BATCH 64
#define TOK   1025
#define DIM   256
#define HIDN  1024
#define LAYERS 6
#define NC    1000
#define NF    129
#define MF    513
#define ROWS  (BATCH*TOK)       // 65600
#define NPAT  1024
#define KPE   768
#define TOKP  1088
#define BNF   (BATCH*NF)        // 8256
#define EPS   1e-5f

// ------------------------------ scratch -----------------------------------
__device__ __align__(128) float          g_t   [ROWS*DIM];
__device__ __align__(128) __nv_bfloat16  g_hH  [ROWS*DIM];
__device__ __align__(128) __nv_bfloat16  g_hL  [ROWS*DIM];
__device__ __align__(128) __nv_bfloat16  g_XH  [BATCH*NPAT*KPE];
__device__ __align__(128) __nv_bfloat16  g_XL  [BATCH*NPAT*KPE];
__device__ __align__(128) __nv_bfloat16  g_hidH[ROWS*HIDN];
__device__ __align__(128) __nv_bfloat16  g_hidL[ROWS*HIDN];
__device__ __align__(128) __nv_bfloat16  g_CH  [BNF*TOKP];
__device__ __align__(128) __nv_bfloat16  g_CL  [BNF*TOKP];
__device__ __align__(128) __nv_bfloat16  g_SH  [BNF*TOKP];
__device__ __align__(128) __nv_bfloat16  g_SL  [BNF*TOKP];
__device__ __align__(128) float          g_U   [MF*BNF];
__device__ __align__(128) float          g_V   [MF*BNF];
__device__ __align__(128) __nv_bfloat16  g_cwH [DIM*KPE],  g_cwL [DIM*KPE];
__device__ __align__(128) __nv_bfloat16  g_bAH [258*DIM],  g_bAL [258*DIM];
__device__ __align__(128) __nv_bfloat16  g_cBH [MF*TOKP],  g_cBL [MF*TOKP];
__device__ __align__(128) __nv_bfloat16  g_sBH [MF*TOKP],  g_sBL [MF*TOKP];
__device__ __align__(128) __nv_bfloat16  g_w1H [LAYERS*HIDN*DIM], g_w1L [LAYERS*HIDN*DIM];
__device__ __align__(128) __nv_bfloat16  g_w2H [LAYERS*DIM*HIDN], g_w2L [LAYERS*DIM*HIDN];
__device__ __align__(128) float          g_pool[BATCH*DIM];

// --------------------------- PTX helpers -----------------------------------
__device__ __forceinline__ uint32_t smem_u32(const void* p) {
    uint32_t a;
    asm("{ .reg .u64 t; cvta.to.shared.u64 t, %1; cvt.u32.u64 %0, t; }" : "=r"(a) : "l"(p));
    return a;
}
__device__ __forceinline__ void cp16(uint32_t dst, const void* src, bool v) {
    asm volatile("cp.async.cg.shared.global [%0], [%1], 16, %2;"
                 :: "r"(dst), "l"(src), "r"(v ? 16 : 0) : "memory");
}
#define CP_COMMIT() asm volatile("cp.async.commit_group;" ::: "memory")
#define CP_WAIT(n)  asm volatile("cp.async.wait_group %0;" :: "n"(n) : "memory")

#define LDSM4(r, addr) \
    asm volatile("ldmatrix.sync.aligned.m8n8.x4.shared.b16 {%0,%1,%2,%3}, [%4];" \
                 : "=r"((r)[0]), "=r"((r)[1]), "=r"((r)[2]), "=r"((r)[3]) : "r"(addr))

#define MMA(c, a, b0, b1) \
    asm volatile("mma.sync.aligned.m16n8k16.row.col.f32.bf16.bf16.f32 " \
                 "{%0,%1,%2,%3}, {%4,%5,%6,%7}, {%8,%9}, {%0,%1,%2,%3};" \
                 : "+f"((c)[0]), "+f"((c)[1]), "+f"((c)[2]), "+f"((c)[3]) \
                 : "r"((a)[0]), "r"((a)[1]), "r"((a)[2]), "r"((a)[3]), \
                   "r"(b0), "r"(b1))

// SMEM stage: Ah(128x64B) Al Bh(256x64B) Bl, XOR-swizzled rows.
#define A_BYTES 8192
#define B_BYTES 16384
#define STAGEB  (2*A_BYTES + 2*B_BYTES)   // 49152
#define NSTAGE  4
#define SMEM_TOTAL (NSTAGE*STAGEB)        // 196608

__device__ __forceinline__ uint32_t swz(int row, int c) {
    return (uint32_t)(row * 64 + ((c ^ ((row >> 1) & 3)) << 4));
}

// epilogue modes
#define M_PATCH 0
#define M_DFT1  1
#define M_F32   2
#define M_FFN1  3
#define M_FFN2  4

// --------------------------- mma.sync GEMM ---------------------------------
__global__ __launch_bounds__(512, 1) void gemm_mma(
    const __nv_bfloat16* __restrict__ Ah, const __nv_bfloat16* __restrict__ Al, int lda,
    const __nv_bfloat16* __restrict__ Bh, const __nv_bfloat16* __restrict__ Bl, int ldb,
    int M, int Nvalid, int K, int mode, int ldc,
    const float* __restrict__ bias, const float* __restrict__ extra,
    float* __restrict__ outf,
    __nv_bfloat16* __restrict__ o0, __nv_bfloat16* __restrict__ o1,
    __nv_bfloat16* __restrict__ o2, __nv_bfloat16* __restrict__ o3)
{
    extern __shared__ char smc[];
    const uint32_t sb = smem_u32(smc);
    const int tid  = threadIdx.x;
    const int lane = tid & 31;
    const int wid  = tid >> 5;
    const int wm   = wid & 3;      // 4 warps along M (32 rows each)
    const int wn   = wid >> 2;     // 4 warps along N (64 cols each)
    const int mBase = blockIdx.y * 128;
    const int nBase = blockIdx.x * 256;

    const int NCH = K >> 5;

    const int lrow = tid >> 2;
    const int lchk = tid & 3;

    auto load_stage = [&](int c) {
        const int k0 = c << 5;
        const uint32_t stg = sb + (uint32_t)(c & (NSTAGE - 1)) * STAGEB;
        {
            const int gm = mBase + lrow;
            const bool ok = gm < M;
            const size_t ro = (size_t)(ok ? gm : 0) * lda + k0 + lchk * 8;
            const uint32_t d = stg + swz(lrow, lchk);
            cp16(d,           Ah + ro, ok);
            cp16(d + A_BYTES, Al + ro, ok);
        }
        {
            const uint32_t bbase = stg + 2 * A_BYTES;
#pragma unroll
            for (int half = 0; half < 2; half++) {
                const int row = lrow + half * 128;
                const int gn = nBase + row;
                const bool ok = gn < Nvalid;
                const size_t ro = (size_t)(ok ? gn : 0) * ldb + k0 + lchk * 8;
                const uint32_t d = bbase + swz(row, lchk);
                cp16(d,           Bh + ro, ok);
                cp16(d + B_BYTES, Bl + ro, ok);
            }
        }
    };

    float acc[2][8][4];
#pragma unroll
    for (int mt = 0; mt < 2; mt++)
#pragma unroll
        for (int nt = 0; nt < 8; nt++)
#pragma unroll
            for (int e = 0; e < 4; e++) acc[mt][nt][e] = 0.f;

    // prologue: stages 0..2
    for (int c = 0; c < NSTAGE - 1; c++) {
        if (c < NCH) load_stage(c);
        CP_COMMIT();
    }

    // B-fragment ldsm address precompute (per ks the chk differs)
    const int brow_lo = wn * 64 + ((lane >> 4) << 3) + (lane & 7);
    const int bsel    = (lane >> 3) & 1;

    for (int c = 0; c < NCH; c++) {
        CP_WAIT(2);            // stage c resident
        __syncthreads();       // all warps done with stage c-1 (single barrier)
        if (c + NSTAGE - 1 < NCH) load_stage(c + NSTAGE - 1);
        CP_COMMIT();

        const uint32_t stg = sb + (uint32_t)(c & (NSTAGE - 1)) * STAGEB;
        const uint32_t baB = stg + 2 * A_BYTES;

#pragma unroll
        for (int ks = 0; ks < 2; ks++) {
            uint32_t aH[2][4], aL[2][4];
#pragma unroll
            for (int mt = 0; mt < 2; mt++) {
                const int row = wm * 32 + mt * 16 + (lane & 15);
                const int chk = ks * 2 + (lane >> 4);
                const uint32_t ad = stg + swz(row, chk);
                LDSM4(aH[mt], ad);
                LDSM4(aL[mt], ad + A_BYTES);
            }
            // register double-buffered B fragments
            uint32_t bH[2][4], bL[2][4];
            {
                const uint32_t ad = baB + swz(brow_lo, ks * 2 + bsel);
                LDSM4(bH[0], ad);
                LDSM4(bL[0], ad + B_BYTES);
            }
#pragma unroll
            for (int nt2 = 0; nt2 < 4; nt2++) {
                const int cur = nt2 & 1;
                if (nt2 < 3) {
                    const uint32_t ad = baB + swz(brow_lo + (nt2 + 1) * 16, ks * 2 + bsel);
                    LDSM4(bH[cur ^ 1], ad);
                    LDSM4(bL[cur ^ 1], ad + B_BYTES);
                }
#pragma unroll
                for (int h = 0; h < 2; h++) {
                    const int nt = nt2 * 2 + h;
#pragma unroll
                    for (int mt = 0; mt < 2; mt++) {
                        MMA(acc[mt][nt], aH[mt], bH[cur][h * 2], bH[cur][h * 2 + 1]);
                        MMA(acc[mt][nt], aH[mt], bL[cur][h * 2], bL[cur][h * 2 + 1]);
                        MMA(acc[mt][nt], aL[mt], bH[cur][h * 2], bH[cur][h * 2 + 1]);
                    }
                }
            }
        }
    }

    // ------------------------------ epilogue -------------------------------
#pragma unroll
    for (int mt = 0; mt < 2; mt++) {
#pragma unroll
        for (int nt = 0; nt < 8; nt++) {
#pragma unroll
            for (int e = 0; e < 4; e++) {
                const int gm = mBase + wm * 32 + mt * 16 + (lane >> 2) + ((e >> 1) << 3);
                const int n  = nBase + wn * 64 + nt * 8 + ((lane & 3) << 1) + (e & 1);
                if (gm >= M || n >= Nvalid) continue;
                const float val = acc[mt][nt][e];
                if (mode == M_PATCH) {
                    const int b = gm >> 10, p = gm & 1023;
                    outf[((size_t)(b * TOK + p + 1)) * DIM + n] =
                        val + bias[n] + extra[(size_t)(p + 1) * DIM + n];
                } else if (mode == M_DFT1) {
                    const bool isCos = (gm < NF);
                    const int nf = isCos ? gm : gm - NF;
                    const int b = n / TOK;
                    const int j = n - b * TOK;
                    const size_t off = ((size_t)(b * NF + nf)) * TOKP + j;
                    const __nv_bfloat16 hi = __float2bfloat16(val);
                    if (isCos) { o0[off] = hi; o1[off] = __float2bfloat16(val - __bfloat162float(hi)); }
                    else       { o2[off] = hi; o3[off] = __float2bfloat16(val - __bfloat162float(hi)); }
                } else if (mode == M_F32) {
                    outf[(size_t)gm * ldc + n] = val;
                } else if (mode == M_FFN1) {
                    float v = val + bias[n];
                    v = v > 0.f ? v : 0.01f * v;
                    const size_t off = (size_t)gm * ldc + n;
                    const __nv_bfloat16 hi = __float2bfloat16(v);
                    o0[off] = hi;
                    o1[off] = __float2bfloat16(v - __bfloat162float(hi));
                } else { // M_FFN2
                    const size_t off = (size_t)gm * ldc + n;
                    outf[off] = outf[off] + val + bias[n];
                }
            }
        }
    }
}

// ------------------------------ prep kernels --------------------------------
__device__ __forceinline__ void store_pair(__nv_bfloat16* h, __nv_bfloat16* l,
                                           size_t i, float v) {
    const __nv_bfloat16 hi = __float2bfloat16(v);
    h[i] = hi;
    l[i] = __float2bfloat16(v - __bfloat162float(hi));
}

__global__ void gen_basisA(__nv_bfloat16* bh, __nv_bfloat16* bl) {
    int idx = blockIdx.x * 256 + threadIdx.x;
    if (idx >= 258 * DIM) return;
    int m = idx / DIM, k = idx % DIM;
    int nf = (m < NF) ? m : m - NF;
    int rr = (k * nf) & 255;
    float a = 2.0f * (float)rr / 256.0f;
    float v = (m < NF) ? cospif(a) : sinpif(a);
    store_pair(bh, bl, idx, v);
}
__global__ void gen_basisB(__nv_bfloat16* ch, __nv_bfloat16* cl,
                           __nv_bfloat16* sh, __nv_bfloat16* sl) {
    int idx = blockIdx.x * 256 + threadIdx.x;
    if (idx >= MF * TOKP) return;
    int m = idx / TOKP, j = idx % TOKP;
    float cv = 0.f, sv = 0.f;
    if (j < TOK) {
        int rr = (m * j) % TOK;
        float a = 2.0f * (float)rr / (float)TOK;
        cv = cospif(a); sv = sinpif(a);
    }
    store_pair(ch, cl, idx, cv);
    store_pair(sh, sl, idx, sv);
}
__global__ void split_convw(const float* __restrict__ w,
                            __nv_bfloat16* h, __nv_bfloat16* l) {
    int idx = blockIdx.x * 256 + threadIdx.x;
    if (idx >= DIM * KPE) return;
    store_pair(h, l, idx, w[idx]);
}
__global__ void tsplit_w1(const float* __restrict__ w,
                          __nv_bfloat16* h, __nv_bfloat16* l) {
    int idx = blockIdx.x * 256 + threadIdx.x;
    if (idx >= LAYERS * HIDN * DIM) return;
    int l_ = idx / (HIDN * DIM);
    int rem = idx - l_ * HIDN * DIM;
    int n = rem / DIM, k = rem % DIM;
    store_pair(h, l, idx, w[(size_t)l_ * DIM * HIDN + (size_t)k * HIDN + n]);
}
__global__ void tsplit_w2(const float* __restrict__ w,
                          __nv_bfloat16* h, __nv_bfloat16* l) {
    int idx = blockIdx.x * 256 + threadIdx.x;
    if (idx >= LAYERS * DIM * HIDN) return;
    int l_ = idx / (DIM * HIDN);
    int rem = idx - l_ * DIM * HIDN;
    int n = rem / HIDN, k = rem % HIDN;
    store_pair(h, l, idx, w[(size_t)l_ * HIDN * DIM + (size_t)k * DIM + n]);
}
__global__ void zeropad_CS(__nv_bfloat16* a, __nv_bfloat16* b,
                           __nv_bfloat16* c, __nv_bfloat16* d) {
    int idx = blockIdx.x * 256 + threadIdx.x;
    const int PADC = TOKP - TOK;
    if (idx >= BNF * PADC) return;
    int rr = idx / PADC, cc = TOK + idx % PADC;
    size_t off = (size_t)rr * TOKP + cc;
    __nv_bfloat16 z = __float2bfloat16(0.f);
    a[off] = z; b[off] = z; c[off] = z; d[off] = z;
}
__global__ void im2col_pair(const float* __restrict__ x,
                            __nv_bfloat16* __restrict__ Xh, __nv_bfloat16* __restrict__ Xl) {
    size_t idx = (size_t)blockIdx.x * 256 + threadIdx.x;
    if (idx >= (size_t)BATCH * NPAT * KPE) return;
    int k = (int)(idx % KPE);
    size_t r = idx / KPE;
    int pr = (int)(r % NPAT);
    int b = (int)(r / NPAT);
    int gh = pr >> 5, gw = pr & 31;
    int c = k >> 8, rem = k & 255, p = rem >> 4, q = rem & 15;
    float v = x[(((size_t)(b * 3 + c) * 512) + gh * 16 + p) * 512 + gw * 16 + q];
    store_pair(Xh, Xl, idx, v);
}
__global__ void cls_kernel(const float* __restrict__ cls, const float* __restrict__ pos,
                           float* __restrict__ t) {
    int idx = blockIdx.x * 256 + threadIdx.x;
    if (idx >= BATCH * DIM) return;
    int b = idx >> 8, n = idx & 255;
    t[(size_t)b * TOK * DIM + n] = cls[n] + pos[n];
}
__global__ void ln_pair(const float* __restrict__ in,
                        __nv_bfloat16* __restrict__ oh, __nv_bfloat16* __restrict__ ol,
                        const float* __restrict__ s, const float* __restrict__ bb, int rows) {
    const int warp = threadIdx.x >> 5;
    const int lane = threadIdx.x & 31;
    const int row = blockIdx.x * 8 + warp;
    if (row >= rows) return;
    const float* p = in + (size_t)row * DIM;
    float v[8], sum = 0.f;
#pragma unroll
    for (int i = 0; i < 8; i++) { v[i] = p[lane + 32 * i]; sum += v[i]; }
#pragma unroll
    for (int o = 16; o; o >>= 1) sum += __shfl_xor_sync(0xffffffffu, sum, o);
    const float mean = sum * (1.f / 256.f);
    float var = 0.f;
#pragma unroll
    for (int i = 0; i < 8; i++) { float d = v[i] - mean; var += d * d; }
#pragma unroll
    for (int o = 16; o; o >>= 1) var += __shfl_xor_sync(0xffffffffu, var, o);
    const float rs = rsqrtf(var * (1.f / 256.f) + EPS);
    const size_t ro = (size_t)row * DIM;
#pragma unroll
    for (int i = 0; i < 8; i++) {
        int n = lane + 32 * i;
        store_pair(oh, ol, ro + n, (v[i] - mean) * rs * s[n] + bb[n]);
    }
}
__global__ void scatter_kernel(const float* __restrict__ U, const float* __restrict__ V,
                               float* __restrict__ t) {
    int idx = blockIdx.x * 256 + threadIdx.x;
    if (idx >= MF * BNF) return;
    int nf = idx % NF;
    int tmp = idx / NF;
    int b = tmp % BATCH;
    int m = tmp / BATCH;
    size_t uoff = (size_t)m * BNF + b * NF + nf;
    float u = U[uoff], v = V[uoff];
    float d1 = u - v, d2 = u + v;
    float* tb = t + (size_t)b * TOK * DIM;
    tb[m * DIM + nf] += d1;
    bool nmir = (nf >= 1 && nf <= 127);
    if (nmir) tb[m * DIM + (DIM - nf)] += d2;
    if (m >= 1) {
        int m2 = TOK - m;
        tb[m2 * DIM + nf] += d2;
        if (nmir) tb[m2 * DIM + (DIM - nf)] += d1;
    }
}
__global__ void pool_kernel(const float* __restrict__ t, float* __restrict__ pooled) {
    int b = blockIdx.x, n = threadIdx.x;
    const float* p = t + (size_t)b * TOK * DIM + n;
    float s0 = 0.f, s1 = 0.f, s2 = 0.f, s3 = 0.f;
    int j = 0;
    for (; j + 4 <= TOK; j += 4) {
        s0 += p[(size_t)(j + 0) * DIM];
        s1 += p[(size_t)(j + 1) * DIM];
        s2 += p[(size_t)(j + 2) * DIM];
        s3 += p[(size_t)(j + 3) * DIM];
    }
    for (; j < TOK; j++) s0 += p[(size_t)j * DIM];
    pooled[b * DIM + n] = (s0 + s1 + s2 + s3) * (1.0f / (float)TOK);
}
__global__ void head_kernel(const float* __restrict__ pooled,
                            const float* __restrict__ hs, const float* __restrict__ hb,
                            const float* __restrict__ W, const float* __restrict__ wb,
                            float* __restrict__ out) {
    __shared__ float sln[DIM];
    __shared__ float red[8];
    const int b = blockIdx.x, tid = threadIdx.x;
    const int lane = tid & 31, warp = tid >> 5;

    float x = pooled[b * DIM + tid];
    float sum = x;
#pragma unroll
    for (int o = 16; o; o >>= 1) sum += __shfl_xor_sync(0xffffffffu, sum, o);
    if (lane == 0) red[warp] = sum;
    __syncthreads();
    float mean;
    {
        float t0 = (lane < 8) ? red[lane] : 0.f;
#pragma unroll
        for (int o = 4; o; o >>= 1) t0 += __shfl_xor_sync(0xffffffffu, t0, o);
        mean = __shfl_sync(0xffffffffu, t0, 0) * (1.f / 256.f);
    }
    __syncthreads();
    float d = x - mean;
    float vv = d * d;
#pragma unroll
    for (int o = 16; o; o >>= 1) vv += __shfl_xor_sync(0xffffffffu, vv, o);
    if (lane == 0) red[warp] = vv;
    __syncthreads();
    float var;
    {
        float t0 = (lane < 8) ? red[lane] : 0.f;
#pragma unroll
        for (int o = 4; o; o >>= 1) t0 += __shfl_xor_sync(0xffffffffu, t0, o);
        var = __shfl_sync(0xffffffffu, t0, 0) * (1.f / 256.f);
    }
    float rs = rsqrtf(var + EPS);
    sln[tid] = d * rs * hs[tid] + hb[tid];
    __syncthreads();

    float lg[4];
#pragma unroll
    for (int jj = 0; jj < 4; jj++) {
        int n = tid + jj * 256;
        float a = 0.f;
        if (n < NC) {
            for (int k = 0; k < DIM; k++) a += sln[k] * W[(size_t)k * NC + n];
            a += wb[n];
        }
        lg[jj] = a;
    }
    float mx = -3.4e38f;
#pragma unroll
    for (int jj = 0; jj < 4; jj++) if (tid + jj * 256 < NC && lg[jj] > mx) mx = lg[jj];
#pragma unroll
    for (int o = 16; o; o >>= 1) mx = fmaxf(mx, __shfl_xor_sync(0xffffffffu, mx, o));
    __syncthreads();
    if (lane == 0) red[warp] = mx;
    __syncthreads();
    {
        float t0 = (lane < 8) ? red[lane] : -3.4e38f;
#pragma unroll
        for (int o = 4; o; o >>= 1) t0 = fmaxf(t0, __shfl_xor_sync(0xffffffffu, t0, o));
        mx = __shfl_sync(0xffffffffu, t0, 0);
    }
    float es = 0.f;
#pragma unroll
    for (int jj = 0; jj < 4; jj++) {
        int n = tid + jj * 256;
        if (n < NC) { lg[jj] = expf(lg[jj] - mx); es += lg[jj]; }
    }
#pragma unroll
    for (int o = 16; o; o >>= 1) es += __shfl_xor_sync(0xffffffffu, es, o);
    __syncthreads();
    if (lane == 0) red[warp] = es;
    __syncthreads();
    {
        float t0 = (lane < 8) ? red[lane] : 0.f;
#pragma unroll
        for (int o = 4; o; o >>= 1) t0 += __shfl_xor_sync(0xffffffffu, t0, o);
        es = __shfl_sync(0xffffffffu, t0, 0);
    }
    float inv = 1.f / es;
#pragma unroll
    for (int jj = 0; jj < 4; jj++) {
        int n = tid + jj * 256;
        if (n < NC) out[(size_t)b * NC + n] = lg[jj] * inv;
    }
}

// ------------------------------ launch ------------------------------------
static inline void run_mma(const __nv_bfloat16* Ah, const __nv_bfloat16* Al, int lda,
                           const __nv_bfloat16* Bh, const __nv_bfloat16* Bl, int ldb,
                           int M, int N, int K, int mode, int ldc,
                           const float* bias, const float* extra, float* outf,
                           __nv_bfloat16* o0 = nullptr, __nv_bfloat16* o1 = nullptr,
                           __nv_bfloat16* o2 = nullptr, __nv_bfloat16* o3 = nullptr)
{
    dim3 grid((N + 255) / 256, (M + 127) / 128);
    gemm_mma<<<grid, 512, SMEM_TOTAL>>>(Ah, Al, lda, Bh, Bl, ldb, M, N, K,
                                        mode, ldc, bias, extra, outf, o0, o1, o2, o3);
}

extern "C" void kernel_launch(void* const* d_in, const int* in_sizes, int n_in,
                              void* d_out, int out_size)
{
    const float* x       = (const float*)d_in[0];
    const float* conv_w  = (const float*)d_in[1];
    const float* conv_b  = (const float*)d_in[2];
    const float* pos_emb = (const float*)d_in[3];
    const float* cls_tok = (const float*)d_in[4];
    const float* ln1_s   = (const float*)d_in[5];
    const float* ln1_b   = (const float*)d_in[6];
    const float* ln2_s   = (const float*)d_in[7];
    const float* ln2_b   = (const float*)d_in[8];
    const float* w1      = (const float*)d_in[9];
    const float* b1      = (const float*)d_in[10];
    const float* w2      = (const float*)d_in[11];
    const float* b2      = (const float*)d_in[12];
    const float* h_ln_s  = (const float*)d_in[13];
    const float* h_ln_b  = (const float*)d_in[14];
    const float* head_w  = (const float*)d_in[15];
    const float* head_b  = (const float*)d_in[16];
    float* out = (float*)d_out;

    float *t, *U, *V, *pl;
    __nv_bfloat16 *hH, *hL, *XH, *XL, *hidH, *hidL;
    __nv_bfloat16 *CH, *CL, *SH, *SL;
    __nv_bfloat16 *cwH, *cwL, *bAH, *bAL, *cBH, *cBL, *sBH, *sBL;
    __nv_bfloat16 *w1H, *w1L, *w2H, *w2L;
    cudaGetSymbolAddress((void**)&t,    g_t);
    cudaGetSymbolAddress((void**)&U,    g_U);
    cudaGetSymbolAddress((void**)&V,    g_V);
    cudaGetSymbolAddress((void**)&pl,   g_pool);
    cudaGetSymbolAddress((void**)&hH,   g_hH);
    cudaGetSymbolAddress((void**)&hL,   g_hL);
    cudaGetSymbolAddress((void**)&XH,   g_XH);
    cudaGetSymbolAddress((void**)&XL,   g_XL);
    cudaGetSymbolAddress((void**)&hidH, g_hidH);
    cudaGetSymbolAddress((void**)&hidL, g_hidL);
    cudaGetSymbolAddress((void**)&CH,   g_CH);
    cudaGetSymbolAddress((void**)&CL,   g_CL);
    cudaGetSymbolAddress((void**)&SH,   g_SH);
    cudaGetSymbolAddress((void**)&SL,   g_SL);
    cudaGetSymbolAddress((void**)&cwH,  g_cwH);
    cudaGetSymbolAddress((void**)&cwL,  g_cwL);
    cudaGetSymbolAddress((void**)&bAH,  g_bAH);
    cudaGetSymbolAddress((void**)&bAL,  g_bAL);
    cudaGetSymbolAddress((void**)&cBH,  g_cBH);
    cudaGetSymbolAddress((void**)&cBL,  g_cBL);
    cudaGetSymbolAddress((void**)&sBH,  g_sBH);
    cudaGetSymbolAddress((void**)&sBL,  g_sBL);
    cudaGetSymbolAddress((void**)&w1H,  g_w1H);
    cudaGetSymbolAddress((void**)&w1L,  g_w1L);
    cudaGetSymbolAddress((void**)&w2H,  g_w2H);
    cudaGetSymbolAddress((void**)&w2L,  g_w2L);

    cudaFuncSetAttribute(gemm_mma, cudaFuncAttributeMaxDynamicSharedMemorySize, SMEM_TOTAL);

    // ---- launch index 3 is what ncu captures -> put the patch GEMM there ----
    im2col_pair<<<(int)(((size_t)BATCH * NPAT * KPE + 255) / 256), 256>>>(x, XH, XL); // 0
    split_convw<<<(DIM * KPE + 255) / 256, 256>>>(conv_w, cwH, cwL);                  // 1
    gen_basisA<<<(258 * DIM + 255) / 256, 256>>>(bAH, bAL);                           // 2
    run_mma(XH, XL, KPE, cwH, cwL, KPE, BATCH * NPAT, DIM, KPE,                       // 3 <- profiled
            M_PATCH, 0, conv_b, pos_emb, t);
    gen_basisB<<<(MF * TOKP + 255) / 256, 256>>>(cBH, cBL, sBH, sBL);
    cls_kernel<<<(BATCH * DIM + 255) / 256, 256>>>(cls_tok, pos_emb, t);
    tsplit_w1<<<(LAYERS * HIDN * DIM + 255) / 256, 256>>>(w1, w1H, w1L);
    tsplit_w2<<<(LAYERS * DIM * HIDN + 255) / 256, 256>>>(w2, w2H, w2L);
    zeropad_CS<<<(BNF * (TOKP - TOK) + 255) / 256, 256>>>(CH, CL, SH, SL);

    for (int i = 0; i < LAYERS; i++) {
        // --- FNet mixing ---
        ln_pair<<<(ROWS + 7) / 8, 256>>>(t, hH, hL, ln1_s + i * DIM, ln1_b + i * DIM, ROWS);
        run_mma(bAH, bAL, DIM, hH, hL, DIM, 258, ROWS, DIM,
                M_DFT1, 0, nullptr, nullptr, nullptr, CH, CL, SH, SL);
        run_mma(cBH, cBL, TOKP, CH, CL, TOKP, MF, BNF, TOKP, M_F32, BNF,
                nullptr, nullptr, U);
        run_mma(sBH, sBL, TOKP, SH, SL, TOKP, MF, BNF, TOKP, M_F32, BNF,
                nullptr, nullptr, V);
        scatter_kernel<<<(MF * BNF + 255) / 256, 256>>>(U, V, t);

        // --- FFN ---
        ln_pair<<<(ROWS + 7) / 8, 256>>>(t, hH, hL, ln2_s + i * DIM, ln2_b + i * DIM, ROWS);
        run_mma(hH, hL, DIM, w1H + (size_t)i * HIDN * DIM, w1L + (size_t)i * HIDN * DIM, DIM,
                ROWS, HIDN, DIM, M_FFN1, HIDN, b1 + i * HIDN, nullptr, nullptr, hidH, hidL);
        run_mma(hidH, hidL, HIDN, w2H + (size_t)i * DIM * HIDN, w2L + (size_t)i * DIM * HIDN, HIDN,
                ROWS, DIM, HIDN, M_FFN2, DIM, b2 + i * DIM, nullptr, t);
    }

    pool_kernel<<<BATCH, DIM>>>(t, pl);
    head_kernel<<<BATCH, DIM>>>(pl, h_ln_s, h_ln_b, head_w, head_b, out);
}